// round 1
// baseline (speedup 1.0000x reference)
#include <cuda_runtime.h>
#include <cstdint>
#include <cstddef>

#define S_DIM 384
#define B_DIM 256
#define CM    256
#define CH    32
#define CZ    128
#define EPSV  1e-5f

// Scratch for projected q/k: layout [b][s][32], fp32.
__device__ float g_q[B_DIM * S_DIM * CH];
__device__ float g_k[B_DIM * S_DIM * CH];

// ---- packed fp32x2 helpers (Blackwell: fma.rn.f32x2 only reachable via PTX) ----
__device__ __forceinline__ unsigned long long dup_f32x2(float x) {
    unsigned long long r;
    asm("mov.b64 %0, {%1, %1};" : "=l"(r) : "r"(__float_as_uint(x)));
    return r;
}
__device__ __forceinline__ unsigned long long pack_f32x2(float lo, float hi) {
    unsigned long long r;
    asm("mov.b64 %0, {%1, %2};" : "=l"(r) : "r"(__float_as_uint(lo)), "r"(__float_as_uint(hi)));
    return r;
}
__device__ __forceinline__ void fma_f32x2(unsigned long long& d,
                                          unsigned long long a,
                                          unsigned long long b) {
    asm("fma.rn.f32x2 %0, %1, %2, %0;" : "+l"(d) : "l"(a), "l"(b));
}
__device__ __forceinline__ float f32x2_lo(unsigned long long v) {
    return __uint_as_float((unsigned)(v & 0xffffffffull));
}
__device__ __forceinline__ float f32x2_hi(unsigned long long v) {
    return __uint_as_float((unsigned)(v >> 32));
}

// ============================================================================
// Kernel A: rmsnorm(m) then q = mn@Wq + bq, k = mn@Wk + bk.
// One warp handles 4 (b,s) rows. Weights staged in shared.
// ============================================================================
__global__ __launch_bounds__(256, 2)
void proj_kernel(const float* __restrict__ m, const float* __restrict__ g_in,
                 const float* __restrict__ Wq, const float* __restrict__ bq,
                 const float* __restrict__ Wk, const float* __restrict__ bk)
{
    extern __shared__ float sm[];
    float* Wq_s = sm;            // 8192 floats
    float* Wk_s = sm + 8192;     // 8192 floats
    float* mn_s = sm + 16384;    // 8 warps * [4][256] = 8192 floats

    const int tid  = threadIdx.x;
    const int warp = tid >> 5;
    const int lane = tid & 31;

    // Cooperative load of weights into shared (2048 float4 each).
    const float4* Wq4 = (const float4*)Wq;
    const float4* Wk4 = (const float4*)Wk;
#pragma unroll
    for (int v = 0; v < 8; ++v) {
        ((float4*)Wq_s)[v * 256 + tid] = Wq4[v * 256 + tid];
        ((float4*)Wk_s)[v * 256 + tid] = Wk4[v * 256 + tid];
    }

    const size_t rb = ((size_t)blockIdx.x * 8 + warp) * 4;  // first of 4 rows
    float* mw = mn_s + warp * 1024;                          // [4][256]

    const float4 gi0 = ((const float4*)g_in)[lane * 2];
    const float4 gi1 = ((const float4*)g_in)[lane * 2 + 1];

    float vals[4][8];
    float ssum[4];
#pragma unroll
    for (int r = 0; r < 4; ++r) {
        const float4* mp = (const float4*)(m + (rb + r) * CM);
        float4 a = mp[lane * 2];
        float4 b = mp[lane * 2 + 1];
        vals[r][0] = a.x; vals[r][1] = a.y; vals[r][2] = a.z; vals[r][3] = a.w;
        vals[r][4] = b.x; vals[r][5] = b.y; vals[r][6] = b.z; vals[r][7] = b.w;
        ssum[r] = a.x*a.x + a.y*a.y + a.z*a.z + a.w*a.w
                + b.x*b.x + b.y*b.y + b.z*b.z + b.w*b.w;
    }
#pragma unroll
    for (int r = 0; r < 4; ++r) {
        float s = ssum[r];
#pragma unroll
        for (int ofs = 16; ofs >= 1; ofs >>= 1)
            s += __shfl_xor_sync(0xffffffffu, s, ofs);
        const float scale = rsqrtf(s * (1.0f / 256.0f) + EPSV);
        float4 o0, o1;
        o0.x = vals[r][0] * scale * gi0.x;
        o0.y = vals[r][1] * scale * gi0.y;
        o0.z = vals[r][2] * scale * gi0.z;
        o0.w = vals[r][3] * scale * gi0.w;
        o1.x = vals[r][4] * scale * gi1.x;
        o1.y = vals[r][5] * scale * gi1.y;
        o1.z = vals[r][6] * scale * gi1.z;
        o1.w = vals[r][7] * scale * gi1.w;
        ((float4*)(mw + r * 256))[lane * 2]     = o0;
        ((float4*)(mw + r * 256))[lane * 2 + 1] = o1;
    }
    __syncthreads();  // weights + mn visible

    float accq[4], acck[4];
    const float bqv = __ldg(bq + lane);
    const float bkv = __ldg(bk + lane);
#pragma unroll
    for (int r = 0; r < 4; ++r) { accq[r] = bqv; acck[r] = bkv; }

#pragma unroll 4
    for (int mm = 0; mm < CM; ++mm) {
        const float wq = Wq_s[mm * 32 + lane];
        const float wk = Wk_s[mm * 32 + lane];
#pragma unroll
        for (int r = 0; r < 4; ++r) {
            const float x = mw[r * 256 + mm];
            accq[r] = fmaf(x, wq, accq[r]);
            acck[r] = fmaf(x, wk, acck[r]);
        }
    }
#pragma unroll
    for (int r = 0; r < 4; ++r) {
        g_q[(rb + r) * 32 + lane] = accq[r];
        g_k[(rb + r) * 32 + lane] = acck[r];
    }
}

// ============================================================================
// Kernel B: fused einsum(b) -> @Wo -> rmsnorm(g_out).
// CTA = 4 i's x 4 j's = 16 (i,j) pairs. 256 threads; each thread owns an
// 8x8 block of one pair's 32x32 A-matrix (as 8x4 f32x2 accumulators).
// ============================================================================
__global__ __launch_bounds__(256, 2)
void fuse_kernel(const float* __restrict__ Wo, const float* __restrict__ bo,
                 const float* __restrict__ g_out, float* __restrict__ out)
{
    extern __shared__ float sm[];
    float* qs  = sm;            // [16][128]  (phase 1)
    float* ks  = sm + 2048;     // [16][128]  (phase 1)
    float* As  = sm;            // [16][1024] (phase 3, overlaps qs/ks)
    float* Wos = sm + 16384;    // [64][128]  (phase 3)

    const int tid = threadIdx.x;
    const int p   = tid >> 4;        // pair 0..15
    const int sub = tid & 15;
    const int ii  = p >> 2;
    const int jj  = p & 3;
    const int c0  = (sub >> 2) * 8;
    const int d0  = (sub & 3) * 8;

    const int i_base = blockIdx.y * 4;
    const int j_base = blockIdx.x * 4;
    const int qgofs  = i_base * 32;   // offset inside g_q row of length 12288
    const int kgofs  = j_base * 32;

    unsigned long long acc[8][4];
#pragma unroll
    for (int r = 0; r < 8; ++r)
#pragma unroll
        for (int s = 0; s < 4; ++s) acc[r][s] = 0ull;

    const int qoff = ii * 32 + c0;
    const int koff = jj * 32 + d0;

    for (int b0 = 0; b0 < B_DIM; b0 += 16) {
        __syncthreads();
#pragma unroll
        for (int v = 0; v < 2; ++v) {
            const int lin = v * 256 + tid;
            const int row = lin >> 5;
            const int col = (lin & 31) * 4;
            *(float4*)(qs + row * 128 + col) =
                *(const float4*)(g_q + (size_t)(b0 + row) * 12288 + qgofs + col);
            *(float4*)(ks + row * 128 + col) =
                *(const float4*)(g_k + (size_t)(b0 + row) * 12288 + kgofs + col);
        }
        __syncthreads();

#pragma unroll 2
        for (int bb = 0; bb < 16; ++bb) {
            const float4 qa = *(const float4*)(qs + bb * 128 + qoff);
            const float4 qb = *(const float4*)(qs + bb * 128 + qoff + 4);
            const ulonglong2 kA = *(const ulonglong2*)(ks + bb * 128 + koff);
            const ulonglong2 kB = *(const ulonglong2*)(ks + bb * 128 + koff + 4);
            const float qv[8] = {qa.x, qa.y, qa.z, qa.w, qb.x, qb.y, qb.z, qb.w};
#pragma unroll
            for (int r = 0; r < 8; ++r) {
                const unsigned long long q2 = dup_f32x2(qv[r]);
                fma_f32x2(acc[r][0], q2, kA.x);
                fma_f32x2(acc[r][1], q2, kA.y);
                fma_f32x2(acc[r][2], q2, kB.x);
                fma_f32x2(acc[r][3], q2, kB.y);
            }
        }
    }
    __syncthreads();  // done reading qs/ks; reuse as As

    // Spill A tiles to shared: As[p][c*32+d]
#pragma unroll
    for (int r = 0; r < 8; ++r)
#pragma unroll
        for (int s = 0; s < 4; ++s)
            *(unsigned long long*)(As + p * 1024 + (c0 + r) * 32 + d0 + 2 * s) = acc[r][s];
    __syncthreads();

    // Phase 3: z[p][zc0..zc0+7] = sum_e A[p][e] * Wo[e][zc]
    const int zc0 = sub * 8;
    unsigned long long z[4];
#pragma unroll
    for (int u = 0; u < 4; ++u)
        z[u] = pack_f32x2(__ldg(bo + zc0 + 2 * u), __ldg(bo + zc0 + 2 * u + 1));

    const float* Arow = As + p * 1024;
    for (int e0 = 0; e0 < 1024; e0 += 64) {
        __syncthreads();
#pragma unroll
        for (int v = 0; v < 8; ++v) {
            const int lin = v * 256 + tid;
            const int row = lin >> 5;
            const int col = (lin & 31) * 4;
            *(float4*)(Wos + row * 128 + col) =
                *(const float4*)(Wo + (size_t)(e0 + row) * 128 + col);
        }
        __syncthreads();
#pragma unroll 4
        for (int e = 0; e < 64; ++e) {
            const unsigned long long a2 = dup_f32x2(Arow[e0 + e]);
            const ulonglong2 w0 = *(const ulonglong2*)(Wos + e * 128 + zc0);
            const ulonglong2 w1 = *(const ulonglong2*)(Wos + e * 128 + zc0 + 4);
            fma_f32x2(z[0], a2, w0.x);
            fma_f32x2(z[1], a2, w0.y);
            fma_f32x2(z[2], a2, w1.x);
            fma_f32x2(z[3], a2, w1.y);
        }
    }

    // Final rmsnorm over 128 channels (spread across the 16 threads of pair p).
    float zv[8];
#pragma unroll
    for (int u = 0; u < 4; ++u) {
        zv[2 * u]     = f32x2_lo(z[u]);
        zv[2 * u + 1] = f32x2_hi(z[u]);
    }
    float ss = 0.0f;
#pragma unroll
    for (int u = 0; u < 8; ++u) ss += zv[u] * zv[u];
    ss += __shfl_xor_sync(0xffffffffu, ss, 1);
    ss += __shfl_xor_sync(0xffffffffu, ss, 2);
    ss += __shfl_xor_sync(0xffffffffu, ss, 4);
    ss += __shfl_xor_sync(0xffffffffu, ss, 8);
    const float scale = rsqrtf(ss * (1.0f / 128.0f) + EPSV);

    const int i = i_base + ii;
    const int j = j_base + jj;
    float* op = out + ((size_t)i * S_DIM + j) * CZ + zc0;
    float4 o0, o1;
    o0.x = zv[0] * scale * __ldg(g_out + zc0 + 0);
    o0.y = zv[1] * scale * __ldg(g_out + zc0 + 1);
    o0.z = zv[2] * scale * __ldg(g_out + zc0 + 2);
    o0.w = zv[3] * scale * __ldg(g_out + zc0 + 3);
    o1.x = zv[4] * scale * __ldg(g_out + zc0 + 4);
    o1.y = zv[5] * scale * __ldg(g_out + zc0 + 5);
    o1.z = zv[6] * scale * __ldg(g_out + zc0 + 6);
    o1.w = zv[7] * scale * __ldg(g_out + zc0 + 7);
    *(float4*)op       = o0;
    *(float4*)(op + 4) = o1;
}

// ============================================================================
extern "C" void kernel_launch(void* const* d_in, const int* in_sizes, int n_in,
                              void* d_out, int out_size)
{
    const float* m    = (const float*)d_in[0];
    const float* g_in = (const float*)d_in[1];
    const float* Wq   = (const float*)d_in[2];
    const float* bq   = (const float*)d_in[3];
    const float* Wk   = (const float*)d_in[4];
    const float* bk   = (const float*)d_in[5];
    const float* Wo   = (const float*)d_in[6];
    const float* bo   = (const float*)d_in[7];
    const float* gout = (const float*)d_in[8];
    float* out = (float*)d_out;

    const int smem = 96 * 1024;  // 24576 floats
    cudaFuncSetAttribute(proj_kernel, cudaFuncAttributeMaxDynamicSharedMemorySize, smem);
    cudaFuncSetAttribute(fuse_kernel, cudaFuncAttributeMaxDynamicSharedMemorySize, smem);

    // Stage 1: 98304 rows, 32 rows/CTA
    proj_kernel<<<(B_DIM * S_DIM) / 32, 256, smem>>>(m, g_in, Wq, bq, Wk, bk);
    // Stage 2+3+norm: 96x96 tiles of 4x4 (i,j) pairs
    fuse_kernel<<<dim3(S_DIM / 4, S_DIM / 4), 256, smem>>>(Wo, bo, gout, out);
}

// round 2
// speedup vs baseline: 1.0001x; 1.0001x over previous
#include <cuda_runtime.h>
#include <cstdint>
#include <cstddef>

#define S_DIM 384
#define B_DIM 256
#define CM    256
#define CH    32
#define CZ    128
#define EPSV  1e-5f

// Scratch for projected q/k: layout [b][s][32], fp32.
__device__ float g_q[B_DIM * S_DIM * CH];
__device__ float g_k[B_DIM * S_DIM * CH];

// ---- packed fp32x2 helpers (Blackwell: fma.rn.f32x2 only reachable via PTX) ----
__device__ __forceinline__ unsigned long long dup_f32x2(float x) {
    unsigned long long r;
    asm("mov.b64 %0, {%1, %1};" : "=l"(r) : "r"(__float_as_uint(x)));
    return r;
}
__device__ __forceinline__ unsigned long long pack_f32x2(float lo, float hi) {
    unsigned long long r;
    asm("mov.b64 %0, {%1, %2};" : "=l"(r) : "r"(__float_as_uint(lo)), "r"(__float_as_uint(hi)));
    return r;
}
__device__ __forceinline__ void fma_f32x2(unsigned long long& d,
                                          unsigned long long a,
                                          unsigned long long b) {
    asm("fma.rn.f32x2 %0, %1, %2, %0;" : "+l"(d) : "l"(a), "l"(b));
}
__device__ __forceinline__ float f32x2_lo(unsigned long long v) {
    return __uint_as_float((unsigned)(v & 0xffffffffull));
}
__device__ __forceinline__ float f32x2_hi(unsigned long long v) {
    return __uint_as_float((unsigned)(v >> 32));
}

// ============================================================================
// Kernel A: rmsnorm(m) then q = mn@Wq + bq, k = mn@Wk + bk.
// One warp handles 4 (b,s) rows. Weights staged in shared.
// ============================================================================
__global__ __launch_bounds__(256, 2)
void proj_kernel(const float* __restrict__ m, const float* __restrict__ g_in,
                 const float* __restrict__ Wq, const float* __restrict__ bq,
                 const float* __restrict__ Wk, const float* __restrict__ bk)
{
    extern __shared__ float sm[];
    float* Wq_s = sm;            // 8192 floats
    float* Wk_s = sm + 8192;     // 8192 floats
    float* mn_s = sm + 16384;    // 8 warps * [4][256] = 8192 floats

    const int tid  = threadIdx.x;
    const int warp = tid >> 5;
    const int lane = tid & 31;

    // Cooperative load of weights into shared (2048 float4 each).
    const float4* Wq4 = (const float4*)Wq;
    const float4* Wk4 = (const float4*)Wk;
#pragma unroll
    for (int v = 0; v < 8; ++v) {
        ((float4*)Wq_s)[v * 256 + tid] = Wq4[v * 256 + tid];
        ((float4*)Wk_s)[v * 256 + tid] = Wk4[v * 256 + tid];
    }

    const size_t rb = ((size_t)blockIdx.x * 8 + warp) * 4;  // first of 4 rows
    float* mw = mn_s + warp * 1024;                          // [4][256]

    const float4 gi0 = ((const float4*)g_in)[lane * 2];
    const float4 gi1 = ((const float4*)g_in)[lane * 2 + 1];

    float vals[4][8];
    float ssum[4];
#pragma unroll
    for (int r = 0; r < 4; ++r) {
        const float4* mp = (const float4*)(m + (rb + r) * CM);
        float4 a = mp[lane * 2];
        float4 b = mp[lane * 2 + 1];
        vals[r][0] = a.x; vals[r][1] = a.y; vals[r][2] = a.z; vals[r][3] = a.w;
        vals[r][4] = b.x; vals[r][5] = b.y; vals[r][6] = b.z; vals[r][7] = b.w;
        ssum[r] = a.x*a.x + a.y*a.y + a.z*a.z + a.w*a.w
                + b.x*b.x + b.y*b.y + b.z*b.z + b.w*b.w;
    }
#pragma unroll
    for (int r = 0; r < 4; ++r) {
        float s = ssum[r];
#pragma unroll
        for (int ofs = 16; ofs >= 1; ofs >>= 1)
            s += __shfl_xor_sync(0xffffffffu, s, ofs);
        const float scale = rsqrtf(s * (1.0f / 256.0f) + EPSV);
        float4 o0, o1;
        o0.x = vals[r][0] * scale * gi0.x;
        o0.y = vals[r][1] * scale * gi0.y;
        o0.z = vals[r][2] * scale * gi0.z;
        o0.w = vals[r][3] * scale * gi0.w;
        o1.x = vals[r][4] * scale * gi1.x;
        o1.y = vals[r][5] * scale * gi1.y;
        o1.z = vals[r][6] * scale * gi1.z;
        o1.w = vals[r][7] * scale * gi1.w;
        ((float4*)(mw + r * 256))[lane * 2]     = o0;
        ((float4*)(mw + r * 256))[lane * 2 + 1] = o1;
    }
    __syncthreads();  // weights + mn visible

    float accq[4], acck[4];
    const float bqv = __ldg(bq + lane);
    const float bkv = __ldg(bk + lane);
#pragma unroll
    for (int r = 0; r < 4; ++r) { accq[r] = bqv; acck[r] = bkv; }

#pragma unroll 4
    for (int mm = 0; mm < CM; ++mm) {
        const float wq = Wq_s[mm * 32 + lane];
        const float wk = Wk_s[mm * 32 + lane];
#pragma unroll
        for (int r = 0; r < 4; ++r) {
            const float x = mw[r * 256 + mm];
            accq[r] = fmaf(x, wq, accq[r]);
            acck[r] = fmaf(x, wk, acck[r]);
        }
    }
#pragma unroll
    for (int r = 0; r < 4; ++r) {
        g_q[(rb + r) * 32 + lane] = accq[r];
        g_k[(rb + r) * 32 + lane] = acck[r];
    }
}

// ============================================================================
// Kernel B: fused einsum(b) -> @Wo -> rmsnorm(g_out).
// CTA = 4 i's x 4 j's = 16 (i,j) pairs. 256 threads; each thread owns an
// 8x8 block of one pair's 32x32 A-matrix (as 8x4 f32x2 accumulators).
// ============================================================================
__global__ __launch_bounds__(256, 2)
void fuse_kernel(const float* __restrict__ Wo, const float* __restrict__ bo,
                 const float* __restrict__ g_out, float* __restrict__ out)
{
    extern __shared__ float sm[];
    float* qs  = sm;            // [16][128]  (phase 1)
    float* ks  = sm + 2048;     // [16][128]  (phase 1)
    float* As  = sm;            // [16][1024] (phase 3, overlaps qs/ks)
    float* Wos = sm + 16384;    // [64][128]  (phase 3)

    const int tid = threadIdx.x;
    const int p   = tid >> 4;        // pair 0..15
    const int sub = tid & 15;
    const int ii  = p >> 2;
    const int jj  = p & 3;
    const int c0  = (sub >> 2) * 8;
    const int d0  = (sub & 3) * 8;

    const int i_base = blockIdx.y * 4;
    const int j_base = blockIdx.x * 4;
    const int qgofs  = i_base * 32;   // offset inside g_q row of length 12288
    const int kgofs  = j_base * 32;

    unsigned long long acc[8][4];
#pragma unroll
    for (int r = 0; r < 8; ++r)
#pragma unroll
        for (int s = 0; s < 4; ++s) acc[r][s] = 0ull;

    const int qoff = ii * 32 + c0;
    const int koff = jj * 32 + d0;

    for (int b0 = 0; b0 < B_DIM; b0 += 16) {
        __syncthreads();
#pragma unroll
        for (int v = 0; v < 2; ++v) {
            const int lin = v * 256 + tid;
            const int row = lin >> 5;
            const int col = (lin & 31) * 4;
            *(float4*)(qs + row * 128 + col) =
                *(const float4*)(g_q + (size_t)(b0 + row) * 12288 + qgofs + col);
            *(float4*)(ks + row * 128 + col) =
                *(const float4*)(g_k + (size_t)(b0 + row) * 12288 + kgofs + col);
        }
        __syncthreads();

#pragma unroll 2
        for (int bb = 0; bb < 16; ++bb) {
            const float4 qa = *(const float4*)(qs + bb * 128 + qoff);
            const float4 qb = *(const float4*)(qs + bb * 128 + qoff + 4);
            const ulonglong2 kA = *(const ulonglong2*)(ks + bb * 128 + koff);
            const ulonglong2 kB = *(const ulonglong2*)(ks + bb * 128 + koff + 4);
            const float qv[8] = {qa.x, qa.y, qa.z, qa.w, qb.x, qb.y, qb.z, qb.w};
#pragma unroll
            for (int r = 0; r < 8; ++r) {
                const unsigned long long q2 = dup_f32x2(qv[r]);
                fma_f32x2(acc[r][0], q2, kA.x);
                fma_f32x2(acc[r][1], q2, kA.y);
                fma_f32x2(acc[r][2], q2, kB.x);
                fma_f32x2(acc[r][3], q2, kB.y);
            }
        }
    }
    __syncthreads();  // done reading qs/ks; reuse as As

    // Spill A tiles to shared: As[p][c*32+d]
#pragma unroll
    for (int r = 0; r < 8; ++r)
#pragma unroll
        for (int s = 0; s < 4; ++s)
            *(unsigned long long*)(As + p * 1024 + (c0 + r) * 32 + d0 + 2 * s) = acc[r][s];
    __syncthreads();

    // Phase 3: z[p][zc0..zc0+7] = sum_e A[p][e] * Wo[e][zc]
    const int zc0 = sub * 8;
    unsigned long long z[4];
#pragma unroll
    for (int u = 0; u < 4; ++u)
        z[u] = pack_f32x2(__ldg(bo + zc0 + 2 * u), __ldg(bo + zc0 + 2 * u + 1));

    const float* Arow = As + p * 1024;
    for (int e0 = 0; e0 < 1024; e0 += 64) {
        __syncthreads();
#pragma unroll
        for (int v = 0; v < 8; ++v) {
            const int lin = v * 256 + tid;
            const int row = lin >> 5;
            const int col = (lin & 31) * 4;
            *(float4*)(Wos + row * 128 + col) =
                *(const float4*)(Wo + (size_t)(e0 + row) * 128 + col);
        }
        __syncthreads();
#pragma unroll 4
        for (int e = 0; e < 64; ++e) {
            const unsigned long long a2 = dup_f32x2(Arow[e0 + e]);
            const ulonglong2 w0 = *(const ulonglong2*)(Wos + e * 128 + zc0);
            const ulonglong2 w1 = *(const ulonglong2*)(Wos + e * 128 + zc0 + 4);
            fma_f32x2(z[0], a2, w0.x);
            fma_f32x2(z[1], a2, w0.y);
            fma_f32x2(z[2], a2, w1.x);
            fma_f32x2(z[3], a2, w1.y);
        }
    }

    // Final rmsnorm over 128 channels (spread across the 16 threads of pair p).
    float zv[8];
#pragma unroll
    for (int u = 0; u < 4; ++u) {
        zv[2 * u]     = f32x2_lo(z[u]);
        zv[2 * u + 1] = f32x2_hi(z[u]);
    }
    float ss = 0.0f;
#pragma unroll
    for (int u = 0; u < 8; ++u) ss += zv[u] * zv[u];
    ss += __shfl_xor_sync(0xffffffffu, ss, 1);
    ss += __shfl_xor_sync(0xffffffffu, ss, 2);
    ss += __shfl_xor_sync(0xffffffffu, ss, 4);
    ss += __shfl_xor_sync(0xffffffffu, ss, 8);
    const float scale = rsqrtf(ss * (1.0f / 128.0f) + EPSV);

    const int i = i_base + ii;
    const int j = j_base + jj;
    float* op = out + ((size_t)i * S_DIM + j) * CZ + zc0;
    float4 o0, o1;
    o0.x = zv[0] * scale * __ldg(g_out + zc0 + 0);
    o0.y = zv[1] * scale * __ldg(g_out + zc0 + 1);
    o0.z = zv[2] * scale * __ldg(g_out + zc0 + 2);
    o0.w = zv[3] * scale * __ldg(g_out + zc0 + 3);
    o1.x = zv[4] * scale * __ldg(g_out + zc0 + 4);
    o1.y = zv[5] * scale * __ldg(g_out + zc0 + 5);
    o1.z = zv[6] * scale * __ldg(g_out + zc0 + 6);
    o1.w = zv[7] * scale * __ldg(g_out + zc0 + 7);
    *(float4*)op       = o0;
    *(float4*)(op + 4) = o1;
}

// ============================================================================
extern "C" void kernel_launch(void* const* d_in, const int* in_sizes, int n_in,
                              void* d_out, int out_size)
{
    const float* m    = (const float*)d_in[0];
    const float* g_in = (const float*)d_in[1];
    const float* Wq   = (const float*)d_in[2];
    const float* bq   = (const float*)d_in[3];
    const float* Wk   = (const float*)d_in[4];
    const float* bk   = (const float*)d_in[5];
    const float* Wo   = (const float*)d_in[6];
    const float* bo   = (const float*)d_in[7];
    const float* gout = (const float*)d_in[8];
    float* out = (float*)d_out;

    const int smem = 96 * 1024;  // 24576 floats
    cudaFuncSetAttribute(proj_kernel, cudaFuncAttributeMaxDynamicSharedMemorySize, smem);
    cudaFuncSetAttribute(fuse_kernel, cudaFuncAttributeMaxDynamicSharedMemorySize, smem);

    // Stage 1: 98304 rows, 32 rows/CTA
    proj_kernel<<<(B_DIM * S_DIM) / 32, 256, smem>>>(m, g_in, Wq, bq, Wk, bk);
    // Stage 2+3+norm: 96x96 tiles of 4x4 (i,j) pairs
    fuse_kernel<<<dim3(S_DIM / 4, S_DIM / 4), 256, smem>>>(Wo, bo, gout, out);
}

// round 4
// speedup vs baseline: 6.3151x; 6.3144x over previous
#include <cuda_runtime.h>
#include <cstdint>
#include <cstddef>

#define EPSV 1e-5f

// g_q/g_k: [(s*32+c)*256 + b]  — GEMM1 operand rows (m=(s,c)), K(=b)-contiguous
__device__ float g_q[384 * 32 * 256];
__device__ float g_k[384 * 32 * 256];
// g_wo: 32 k-slices, each the ready smem image: [n=128][32 floats, XOR-swizzled]
__device__ float g_wo[32 * 4096];
// g_a: [p = i*384+j][e = c*32+d]  row-major — GEMM2 A operand
__device__ float g_a[150994944];  // 147456 * 1024 floats = 604 MB

// ---------------- helpers ----------------
__device__ __forceinline__ uint32_t smem_u32(const void* p) {
    uint32_t a;
    asm("{ .reg .u64 t; cvta.to.shared.u64 t, %1; cvt.u32.u64 %0, t; }" : "=r"(a) : "l"(p));
    return a;
}
__device__ __forceinline__ float f2tf32(float x) {
    uint32_t r;
    asm("cvt.rna.tf32.f32 %0, %1;" : "=r"(r) : "f"(x));
    return __uint_as_float(r);
}
#define CP_ASYNC16(dst, src) \
    asm volatile("cp.async.cg.shared.global [%0], [%1], 16;" :: "r"(dst), "l"(src))
#define CP_COMMIT() asm volatile("cp.async.commit_group;")
#define CP_WAIT1()  asm volatile("cp.async.wait_group 1;")
#define CP_WAIT0()  asm volatile("cp.async.wait_group 0;")

__device__ __forceinline__ void mma_tf32(float* d, uint32_t a0, uint32_t a1,
                                         uint32_t a2, uint32_t a3,
                                         uint32_t b0, uint32_t b1) {
    asm volatile(
        "mma.sync.aligned.m16n8k8.row.col.f32.tf32.tf32.f32 "
        "{%0,%1,%2,%3}, {%4,%5,%6,%7}, {%8,%9}, {%0,%1,%2,%3};"
        : "+f"(d[0]), "+f"(d[1]), "+f"(d[2]), "+f"(d[3])
        : "r"(a0), "r"(a1), "r"(a2), "r"(a3), "r"(b0), "r"(b1));
}

// ============================================================================
// proj: rmsnorm(m)*g_in -> q/k projections -> tf32-rounded transposed store
// ============================================================================
__global__ __launch_bounds__(256, 2)
void proj_kernel(const float* __restrict__ m, const float* __restrict__ g_in,
                 const float* __restrict__ Wq, const float* __restrict__ bq,
                 const float* __restrict__ Wk, const float* __restrict__ bk)
{
    extern __shared__ float sm[];
    float* Wq_s = sm;
    float* Wk_s = sm + 8192;
    float* mn_s = sm + 16384;
    const int tid = threadIdx.x, warp = tid >> 5, lane = tid & 31;
    const float4* Wq4 = (const float4*)Wq;
    const float4* Wk4 = (const float4*)Wk;
#pragma unroll
    for (int v = 0; v < 8; ++v) {
        ((float4*)Wq_s)[v * 256 + tid] = Wq4[v * 256 + tid];
        ((float4*)Wk_s)[v * 256 + tid] = Wk4[v * 256 + tid];
    }
    const int rb = (blockIdx.x * 8 + warp) * 4;
    float* mw = mn_s + warp * 1024;
    const float4 gi0 = ((const float4*)g_in)[lane * 2];
    const float4 gi1 = ((const float4*)g_in)[lane * 2 + 1];
    float vals[4][8], ssum[4];
#pragma unroll
    for (int r = 0; r < 4; ++r) {
        const float4* mp = (const float4*)(m + (size_t)(rb + r) * 256);
        float4 a = mp[lane * 2], b = mp[lane * 2 + 1];
        vals[r][0] = a.x; vals[r][1] = a.y; vals[r][2] = a.z; vals[r][3] = a.w;
        vals[r][4] = b.x; vals[r][5] = b.y; vals[r][6] = b.z; vals[r][7] = b.w;
        ssum[r] = a.x*a.x + a.y*a.y + a.z*a.z + a.w*a.w
                + b.x*b.x + b.y*b.y + b.z*b.z + b.w*b.w;
    }
#pragma unroll
    for (int r = 0; r < 4; ++r) {
        float s = ssum[r];
#pragma unroll
        for (int o = 16; o >= 1; o >>= 1) s += __shfl_xor_sync(~0u, s, o);
        const float sc = rsqrtf(s * (1.0f / 256.0f) + EPSV);
        float4 o0, o1;
        o0.x = vals[r][0]*sc*gi0.x; o0.y = vals[r][1]*sc*gi0.y;
        o0.z = vals[r][2]*sc*gi0.z; o0.w = vals[r][3]*sc*gi0.w;
        o1.x = vals[r][4]*sc*gi1.x; o1.y = vals[r][5]*sc*gi1.y;
        o1.z = vals[r][6]*sc*gi1.z; o1.w = vals[r][7]*sc*gi1.w;
        ((float4*)(mw + r * 256))[lane * 2]     = o0;
        ((float4*)(mw + r * 256))[lane * 2 + 1] = o1;
    }
    __syncthreads();
    float aq[4], ak[4];
    const float bqv = __ldg(bq + lane), bkv = __ldg(bk + lane);
#pragma unroll
    for (int r = 0; r < 4; ++r) { aq[r] = bqv; ak[r] = bkv; }
#pragma unroll 4
    for (int mm = 0; mm < 256; ++mm) {
        const float wq = Wq_s[mm * 32 + lane], wk = Wk_s[mm * 32 + lane];
#pragma unroll
        for (int r = 0; r < 4; ++r) {
            const float x = mw[r * 256 + mm];
            aq[r] = fmaf(x, wq, aq[r]);
            ak[r] = fmaf(x, wk, ak[r]);
        }
    }
#pragma unroll
    for (int r = 0; r < 4; ++r) {
        const int row = rb + r, b = row / 384, s = row - b * 384;
        g_q[(size_t)(s * 32 + lane) * 256 + b] = f2tf32(aq[r]);
        g_k[(size_t)(s * 32 + lane) * 256 + b] = f2tf32(ak[r]);
    }
}

// ============================================================================
// wot: Wo[e=ks*32+kk][z=n] -> g_wo[ks][n*32 + swiz(kk,n)] (tf32-rounded)
// ============================================================================
__global__ void wot_kernel(const float* __restrict__ Wo) {
    const int ks = blockIdx.x, n = threadIdx.x;
    float* dst = g_wo + ks * 4096 + n * 32;
    const int n7 = n & 7;
#pragma unroll
    for (int kk = 0; kk < 32; ++kk) {
        const float v = f2tf32(__ldg(Wo + (size_t)(ks * 32 + kk) * 128 + n));
        dst[(((kk >> 2) ^ n7) << 2) | (kk & 3)] = v;
    }
}

// ============================================================================
// gemm1: D[(i,c)][(j,d)] = sum_b q*k  — 128x128x256 per CTA, mma.sync tf32
// smem: buf[2] x (A 4096 + B 4096 floats); epilogue D_s[128][132] overlays.
// ============================================================================
__global__ __launch_bounds__(256, 2)
void gemm1_kernel() {
    extern __shared__ float sm[];
    const int tid = threadIdx.x, w = tid >> 5, l = tid & 31;
    const int mw = w >> 2, nw = w & 3, lg = l >> 2, lm4 = l & 3;
    const int irow = blockIdx.y * 128, jrow = blockIdx.x * 128;
    const uint32_t smb = smem_u32(sm);

    float acc[4][4][4] = {};

    // staging thread mapping (4 float4 per operand per thread)
    int srow[4], sq[4];
    uint32_t sdst[4];
#pragma unroll
    for (int v = 0; v < 4; ++v) {
        const int fl = v * 256 + tid;
        srow[v] = fl >> 3;
        sq[v]   = fl & 7;
        sdst[v] = (uint32_t)((srow[v] * 8 + (sq[v] ^ (srow[v] & 7))) * 16);
    }

#define G1_STAGE(ks, buf) do {                                                  \
    const uint32_t bofs = smb + (buf) * 32768;                                  \
    _Pragma("unroll")                                                           \
    for (int v = 0; v < 4; ++v) {                                               \
        const float* sA = g_q + (size_t)(irow + srow[v]) * 256 + (ks) * 32 + sq[v] * 4; \
        const float* sB = g_k + (size_t)(jrow + srow[v]) * 256 + (ks) * 32 + sq[v] * 4; \
        CP_ASYNC16(bofs + sdst[v], sA);                                         \
        CP_ASYNC16(bofs + 16384 + sdst[v], sB);                                 \
    }                                                                           \
    CP_COMMIT();                                                                \
} while (0)

    G1_STAGE(0, 0);
    for (int ks = 0; ks < 8; ++ks) {
        if (ks + 1 < 8) { G1_STAGE(ks + 1, (ks + 1) & 1); CP_WAIT1(); }
        else            { CP_WAIT0(); }
        __syncthreads();
        const float* As = sm + (ks & 1) * 8192;
        const float* Bs = As + 4096;
#pragma unroll
        for (int s = 0; s < 4; ++s) {
            const int clo = (((2 * s)     ^ lg) << 2) | lm4;
            const int chi = (((2 * s + 1) ^ lg) << 2) | lm4;
            uint32_t b0[4], b1[4];
#pragma unroll
            for (int ni = 0; ni < 4; ++ni) {
                const int nr = (nw * 32 + ni * 8 + lg) * 32;
                b0[ni] = __float_as_uint(Bs[nr + clo]);
                b1[ni] = __float_as_uint(Bs[nr + chi]);
            }
#pragma unroll
            for (int mi = 0; mi < 4; ++mi) {
                const int r0 = (mw * 64 + mi * 16 + lg) * 32;
                const uint32_t A0 = __float_as_uint(As[r0 + clo]);
                const uint32_t A1 = __float_as_uint(As[r0 + 256 + clo]);
                const uint32_t A2 = __float_as_uint(As[r0 + chi]);
                const uint32_t A3 = __float_as_uint(As[r0 + 256 + chi]);
#pragma unroll
                for (int ni = 0; ni < 4; ++ni)
                    mma_tf32(acc[mi][ni], A0, A1, A2, A3, b0[ni], b1[ni]);
            }
        }
        __syncthreads();
    }

    // stage D tile to smem
    float* Ds = sm;
#pragma unroll
    for (int mi = 0; mi < 4; ++mi) {
        const int r0 = mw * 64 + mi * 16 + lg;
#pragma unroll
        for (int ni = 0; ni < 4; ++ni) {
            const int c0 = nw * 32 + ni * 8 + lm4 * 2;
            *(float2*)(Ds + r0 * 132 + c0)       = make_float2(acc[mi][ni][0], acc[mi][ni][1]);
            *(float2*)(Ds + (r0 + 8) * 132 + c0) = make_float2(acc[mi][ni][2], acc[mi][ni][3]);
        }
    }
    __syncthreads();

    // coalesced write-out of 16 pair-rows (1024 floats each), tf32-rounded
    const int pp = tid >> 4, t16 = tid & 15;
    const int ii = pp >> 2, jj = pp & 3;
    const int i = blockIdx.y * 4 + ii, j = blockIdx.x * 4 + jj;
    float* dst = g_a + (size_t)(i * 384 + j) * 1024;
#pragma unroll
    for (int qq = 0; qq < 16; ++qq) {
        const int e = (t16 + qq * 16) * 4;
        const float* sp = Ds + (ii * 32 + (e >> 5)) * 132 + jj * 32 + (e & 31);
        float4 v = *(const float4*)sp;
        v.x = f2tf32(v.x); v.y = f2tf32(v.y); v.z = f2tf32(v.z); v.w = f2tf32(v.w);
        *(float4*)(dst + e) = v;
    }
}

// ============================================================================
// gemm2: z[p][n] = sum_e A[p][e]*Wo[e][n] + bias -> rmsnorm(g_out)
// 128x128x1024 per CTA.
// ============================================================================
__global__ __launch_bounds__(256, 2)
void gemm2_kernel(const float* __restrict__ bo, const float* __restrict__ gout,
                  float* __restrict__ out) {
    extern __shared__ float sm[];
    const int tid = threadIdx.x, w = tid >> 5, l = tid & 31;
    const int mw = w >> 2, nw = w & 3, lg = l >> 2, lm4 = l & 3;
    const int p_base = blockIdx.x * 128;
    const uint32_t smb = smem_u32(sm);

    float acc[4][4][4] = {};

    int srow[4], sq[4];
    uint32_t sdst[4];
#pragma unroll
    for (int v = 0; v < 4; ++v) {
        const int fl = v * 256 + tid;
        srow[v] = fl >> 3;
        sq[v]   = fl & 7;
        sdst[v] = (uint32_t)((srow[v] * 8 + (sq[v] ^ (srow[v] & 7))) * 16);
    }

#define G2_STAGE(ks, buf) do {                                                  \
    const uint32_t bofs = smb + (buf) * 32768;                                  \
    _Pragma("unroll")                                                           \
    for (int v = 0; v < 4; ++v) {                                               \
        const float* sA = g_a + (size_t)(p_base + srow[v]) * 1024 + (ks) * 32 + sq[v] * 4; \
        const int fl = v * 256 + tid;                                           \
        const float* sB = g_wo + (ks) * 4096 + fl * 4;                          \
        CP_ASYNC16(bofs + sdst[v], sA);                                         \
        CP_ASYNC16(bofs + 16384 + (uint32_t)(fl * 16), sB);                     \
    }                                                                           \
    CP_COMMIT();                                                                \
} while (0)

    G2_STAGE(0, 0);
    for (int ks = 0; ks < 32; ++ks) {
        if (ks + 1 < 32) { G2_STAGE(ks + 1, (ks + 1) & 1); CP_WAIT1(); }
        else             { CP_WAIT0(); }
        __syncthreads();
        const float* As = sm + (ks & 1) * 8192;
        const float* Bs = As + 4096;
#pragma unroll
        for (int s = 0; s < 4; ++s) {
            const int clo = (((2 * s)     ^ lg) << 2) | lm4;
            const int chi = (((2 * s + 1) ^ lg) << 2) | lm4;
            uint32_t b0[4], b1[4];
#pragma unroll
            for (int ni = 0; ni < 4; ++ni) {
                const int nr = (nw * 32 + ni * 8 + lg) * 32;
                b0[ni] = __float_as_uint(Bs[nr + clo]);
                b1[ni] = __float_as_uint(Bs[nr + chi]);
            }
#pragma unroll
            for (int mi = 0; mi < 4; ++mi) {
                const int r0 = (mw * 64 + mi * 16 + lg) * 32;
                const uint32_t A0 = __float_as_uint(As[r0 + clo]);
                const uint32_t A1 = __float_as_uint(As[r0 + 256 + clo]);
                const uint32_t A2 = __float_as_uint(As[r0 + chi]);
                const uint32_t A3 = __float_as_uint(As[r0 + 256 + chi]);
#pragma unroll
                for (int ni = 0; ni < 4; ++ni)
                    mma_tf32(acc[mi][ni], A0, A1, A2, A3, b0[ni], b1[ni]);
            }
        }
        __syncthreads();
    }

    float* Ds = sm;
#pragma unroll
    for (int mi = 0; mi < 4; ++mi) {
        const int r0 = mw * 64 + mi * 16 + lg;
#pragma unroll
        for (int ni = 0; ni < 4; ++ni) {
            const int c0 = nw * 32 + ni * 8 + lm4 * 2;
            *(float2*)(Ds + r0 * 132 + c0)       = make_float2(acc[mi][ni][0], acc[mi][ni][1]);
            *(float2*)(Ds + (r0 + 8) * 132 + c0) = make_float2(acc[mi][ni][2], acc[mi][ni][3]);
        }
    }
    __syncthreads();

    // bias + rmsnorm: thread handles half a row (64 z), pair-reduce via shfl
    const int row = tid >> 1, h = tid & 1;
    const float* rp = Ds + row * 132 + h * 64;
    float fv[64];
    float ssq = 0.0f;
#pragma unroll
    for (int q = 0; q < 16; ++q) {
        float4 v = *(const float4*)(rp + q * 4);
        const float4 bb = __ldg((const float4*)(bo + h * 64 + q * 4));
        fv[q * 4 + 0] = v.x + bb.x;
        fv[q * 4 + 1] = v.y + bb.y;
        fv[q * 4 + 2] = v.z + bb.z;
        fv[q * 4 + 3] = v.w + bb.w;
        ssq = fmaf(fv[q*4+0], fv[q*4+0], ssq);
        ssq = fmaf(fv[q*4+1], fv[q*4+1], ssq);
        ssq = fmaf(fv[q*4+2], fv[q*4+2], ssq);
        ssq = fmaf(fv[q*4+3], fv[q*4+3], ssq);
    }
    ssq += __shfl_xor_sync(~0u, ssq, 1);
    const float sc = rsqrtf(ssq * (1.0f / 128.0f) + EPSV);
    float* op = out + (size_t)(p_base + row) * 128 + h * 64;
#pragma unroll
    for (int q = 0; q < 16; ++q) {
        const float4 gg = __ldg((const float4*)(gout + h * 64 + q * 4));
        float4 v;
        v.x = fv[q * 4 + 0] * sc * gg.x;
        v.y = fv[q * 4 + 1] * sc * gg.y;
        v.z = fv[q * 4 + 2] * sc * gg.z;
        v.w = fv[q * 4 + 3] * sc * gg.w;
        *(float4*)(op + q * 4) = v;
    }
}

// ============================================================================
extern "C" void kernel_launch(void* const* d_in, const int* in_sizes, int n_in,
                              void* d_out, int out_size) {
    const float* m    = (const float*)d_in[0];
    const float* g_in = (const float*)d_in[1];
    const float* Wq   = (const float*)d_in[2];
    const float* bq   = (const float*)d_in[3];
    const float* Wk   = (const float*)d_in[4];
    const float* bk   = (const float*)d_in[5];
    const float* Wo   = (const float*)d_in[6];
    const float* bo   = (const float*)d_in[7];
    const float* gout = (const float*)d_in[8];
    float* out = (float*)d_out;

    cudaFuncSetAttribute(proj_kernel,  cudaFuncAttributeMaxDynamicSharedMemorySize, 98304);
    cudaFuncSetAttribute(gemm1_kernel, cudaFuncAttributeMaxDynamicSharedMemorySize, 69632);
    cudaFuncSetAttribute(gemm2_kernel, cudaFuncAttributeMaxDynamicSharedMemorySize, 69632);

    proj_kernel<<<(256 * 384) / 32, 256, 98304>>>(m, g_in, Wq, bq, Wk, bk);
    wot_kernel<<<32, 128>>>(Wo);
    gemm1_kernel<<<dim3(96, 96), 256, 69632>>>();
    gemm2_kernel<<<1152, 256, 69632>>>(bo, gout, out);
}

// round 5
// speedup vs baseline: 6.6053x; 1.0460x over previous
#include <cuda_runtime.h>
#include <cstdint>
#include <cstddef>

#define EPSV 1e-5f

// g_q/g_k: [(s*32+c)*256 + b]  — GEMM1 operand rows (m=(s,c)), K(=b)-contiguous
__device__ float g_q[384 * 32 * 256];
__device__ float g_k[384 * 32 * 256];
// g_wo: 32 k-slices, each the ready smem image: [n=128][32 floats, XOR-swizzled]
__device__ float g_wo[32 * 4096];
// g_a: [p = i*384+j][e = c*32+d]  row-major — GEMM2 A operand
__device__ float g_a[150994944];  // 147456 * 1024 floats = 604 MB

// ---------------- helpers ----------------
__device__ __forceinline__ uint32_t smem_u32(const void* p) {
    uint32_t a;
    asm("{ .reg .u64 t; cvta.to.shared.u64 t, %1; cvt.u32.u64 %0, t; }" : "=r"(a) : "l"(p));
    return a;
}
__device__ __forceinline__ float f2tf32(float x) {
    uint32_t r;
    asm("cvt.rna.tf32.f32 %0, %1;" : "=r"(r) : "f"(x));
    return __uint_as_float(r);
}
#define CP_ASYNC16(dst, src) \
    asm volatile("cp.async.cg.shared.global [%0], [%1], 16;" :: "r"(dst), "l"(src))
#define CP_COMMIT() asm volatile("cp.async.commit_group;")
#define CP_WAIT1()  asm volatile("cp.async.wait_group 1;")
#define CP_WAIT0()  asm volatile("cp.async.wait_group 0;")

__device__ __forceinline__ void mma_tf32(float* d, uint32_t a0, uint32_t a1,
                                         uint32_t a2, uint32_t a3,
                                         uint32_t b0, uint32_t b1) {
    asm volatile(
        "mma.sync.aligned.m16n8k8.row.col.f32.tf32.tf32.f32 "
        "{%0,%1,%2,%3}, {%4,%5,%6,%7}, {%8,%9}, {%0,%1,%2,%3};"
        : "+f"(d[0]), "+f"(d[1]), "+f"(d[2]), "+f"(d[3])
        : "r"(a0), "r"(a1), "r"(a2), "r"(a3), "r"(b0), "r"(b1));
}

// ============================================================================
// proj: rmsnorm(m)*g_in -> q/k projections -> tf32-rounded transposed store
// ============================================================================
__global__ __launch_bounds__(256, 2)
void proj_kernel(const float* __restrict__ m, const float* __restrict__ g_in,
                 const float* __restrict__ Wq, const float* __restrict__ bq,
                 const float* __restrict__ Wk, const float* __restrict__ bk)
{
    extern __shared__ float sm[];
    float* Wq_s = sm;
    float* Wk_s = sm + 8192;
    float* mn_s = sm + 16384;
    const int tid = threadIdx.x, warp = tid >> 5, lane = tid & 31;
    const float4* Wq4 = (const float4*)Wq;
    const float4* Wk4 = (const float4*)Wk;
#pragma unroll
    for (int v = 0; v < 8; ++v) {
        ((float4*)Wq_s)[v * 256 + tid] = Wq4[v * 256 + tid];
        ((float4*)Wk_s)[v * 256 + tid] = Wk4[v * 256 + tid];
    }
    const int rb = (blockIdx.x * 8 + warp) * 4;
    float* mw = mn_s + warp * 1024;
    const float4 gi0 = ((const float4*)g_in)[lane * 2];
    const float4 gi1 = ((const float4*)g_in)[lane * 2 + 1];
    float vals[4][8], ssum[4];
#pragma unroll
    for (int r = 0; r < 4; ++r) {
        const float4* mp = (const float4*)(m + (size_t)(rb + r) * 256);
        float4 a = mp[lane * 2], b = mp[lane * 2 + 1];
        vals[r][0] = a.x; vals[r][1] = a.y; vals[r][2] = a.z; vals[r][3] = a.w;
        vals[r][4] = b.x; vals[r][5] = b.y; vals[r][6] = b.z; vals[r][7] = b.w;
        ssum[r] = a.x*a.x + a.y*a.y + a.z*a.z + a.w*a.w
                + b.x*b.x + b.y*b.y + b.z*b.z + b.w*b.w;
    }
#pragma unroll
    for (int r = 0; r < 4; ++r) {
        float s = ssum[r];
#pragma unroll
        for (int o = 16; o >= 1; o >>= 1) s += __shfl_xor_sync(~0u, s, o);
        const float sc = rsqrtf(s * (1.0f / 256.0f) + EPSV);
        float4 o0, o1;
        o0.x = vals[r][0]*sc*gi0.x; o0.y = vals[r][1]*sc*gi0.y;
        o0.z = vals[r][2]*sc*gi0.z; o0.w = vals[r][3]*sc*gi0.w;
        o1.x = vals[r][4]*sc*gi1.x; o1.y = vals[r][5]*sc*gi1.y;
        o1.z = vals[r][6]*sc*gi1.z; o1.w = vals[r][7]*sc*gi1.w;
        ((float4*)(mw + r * 256))[lane * 2]     = o0;
        ((float4*)(mw + r * 256))[lane * 2 + 1] = o1;
    }
    __syncthreads();
    float aq[4], ak[4];
    const float bqv = __ldg(bq + lane), bkv = __ldg(bk + lane);
#pragma unroll
    for (int r = 0; r < 4; ++r) { aq[r] = bqv; ak[r] = bkv; }
#pragma unroll 4
    for (int mm = 0; mm < 256; ++mm) {
        const float wq = Wq_s[mm * 32 + lane], wk = Wk_s[mm * 32 + lane];
#pragma unroll
        for (int r = 0; r < 4; ++r) {
            const float x = mw[r * 256 + mm];
            aq[r] = fmaf(x, wq, aq[r]);
            ak[r] = fmaf(x, wk, ak[r]);
        }
    }
#pragma unroll
    for (int r = 0; r < 4; ++r) {
        const int row = rb + r, b = row / 384, s = row - b * 384;
        g_q[(size_t)(s * 32 + lane) * 256 + b] = f2tf32(aq[r]);
        g_k[(size_t)(s * 32 + lane) * 256 + b] = f2tf32(ak[r]);
    }
}

// ============================================================================
// wot: Wo[e=ks*32+kk][z=n] -> g_wo[ks][n*32 + swiz(kk,n)] (tf32-rounded)
// ============================================================================
__global__ void wot_kernel(const float* __restrict__ Wo) {
    const int ks = blockIdx.x, n = threadIdx.x;
    float* dst = g_wo + ks * 4096 + n * 32;
    const int n7 = n & 7;
#pragma unroll
    for (int kk = 0; kk < 32; ++kk) {
        const float v = f2tf32(__ldg(Wo + (size_t)(ks * 32 + kk) * 128 + n));
        dst[(((kk >> 2) ^ n7) << 2) | (kk & 3)] = v;
    }
}

// ============================================================================
// Shared compute step: one 32-k chunk of 128x128 MMA from smem buffer.
// ============================================================================
__device__ __forceinline__ void mma_chunk(const float* As, const float* Bs,
                                          float acc[4][4][4],
                                          int mw, int nw, int lg, int lm4) {
#pragma unroll
    for (int s = 0; s < 4; ++s) {
        const int clo = (((2 * s)     ^ lg) << 2) | lm4;
        const int chi = (((2 * s + 1) ^ lg) << 2) | lm4;
        uint32_t b0[4], b1[4];
#pragma unroll
        for (int ni = 0; ni < 4; ++ni) {
            const int nr = (nw * 32 + ni * 8 + lg) * 32;
            b0[ni] = __float_as_uint(Bs[nr + clo]);
            b1[ni] = __float_as_uint(Bs[nr + chi]);
        }
#pragma unroll
        for (int mi = 0; mi < 4; ++mi) {
            const int r0 = (mw * 64 + mi * 16 + lg) * 32;
            const uint32_t A0 = __float_as_uint(As[r0 + clo]);
            const uint32_t A1 = __float_as_uint(As[r0 + 256 + clo]);
            const uint32_t A2 = __float_as_uint(As[r0 + chi]);
            const uint32_t A3 = __float_as_uint(As[r0 + 256 + chi]);
#pragma unroll
            for (int ni = 0; ni < 4; ++ni)
                mma_tf32(acc[mi][ni], A0, A1, A2, A3, b0[ni], b1[ni]);
        }
    }
}

// ============================================================================
// gemm1: D[(i,c)][(j,d)] = sum_b q*k  — 128x128x256, 3-stage pipeline.
// smem: 3 stages x (A 4096 + B 4096 floats) = 96KB; epilogue Ds overlays.
// ============================================================================
__global__ __launch_bounds__(256, 2)
void gemm1_kernel() {
    extern __shared__ float sm[];
    const int tid = threadIdx.x, w = tid >> 5, l = tid & 31;
    const int mw = w >> 2, nw = w & 3, lg = l >> 2, lm4 = l & 3;
    const int irow = blockIdx.y * 128, jrow = blockIdx.x * 128;
    const uint32_t smb = smem_u32(sm);

    float acc[4][4][4] = {};

    int srow[4], sq[4];
    uint32_t sdst[4];
#pragma unroll
    for (int v = 0; v < 4; ++v) {
        const int fl = v * 256 + tid;
        srow[v] = fl >> 3;
        sq[v]   = fl & 7;
        sdst[v] = (uint32_t)((srow[v] * 8 + (sq[v] ^ (srow[v] & 7))) * 16);
    }

#define G1_STAGE(ks, buf) do {                                                  \
    const uint32_t bofs = smb + (uint32_t)(buf) * 32768u;                       \
    _Pragma("unroll")                                                           \
    for (int v = 0; v < 4; ++v) {                                               \
        const float* sA = g_q + (size_t)(irow + srow[v]) * 256 + (ks) * 32 + sq[v] * 4; \
        const float* sB = g_k + (size_t)(jrow + srow[v]) * 256 + (ks) * 32 + sq[v] * 4; \
        CP_ASYNC16(bofs + sdst[v], sA);                                         \
        CP_ASYNC16(bofs + 16384 + sdst[v], sB);                                 \
    }                                                                           \
    CP_COMMIT();                                                                \
} while (0)

    G1_STAGE(0, 0);
    G1_STAGE(1, 1);
#pragma unroll
    for (int ks = 0; ks < 8; ++ks) {
        if (ks + 1 < 8) CP_WAIT1(); else CP_WAIT0();
        __syncthreads();
        if (ks + 2 < 8) G1_STAGE(ks + 2, (ks + 2) % 3);
        const float* As = sm + (ks % 3) * 8192;
        mma_chunk(As, As + 4096, acc, mw, nw, lg, lm4);
    }
    __syncthreads();

    float* Ds = sm;
#pragma unroll
    for (int mi = 0; mi < 4; ++mi) {
        const int r0 = mw * 64 + mi * 16 + lg;
#pragma unroll
        for (int ni = 0; ni < 4; ++ni) {
            const int c0 = nw * 32 + ni * 8 + lm4 * 2;
            *(float2*)(Ds + r0 * 132 + c0)       = make_float2(acc[mi][ni][0], acc[mi][ni][1]);
            *(float2*)(Ds + (r0 + 8) * 132 + c0) = make_float2(acc[mi][ni][2], acc[mi][ni][3]);
        }
    }
    __syncthreads();

    const int pp = tid >> 4, t16 = tid & 15;
    const int ii = pp >> 2, jj = pp & 3;
    const int i = blockIdx.y * 4 + ii, j = blockIdx.x * 4 + jj;
    float* dst = g_a + (size_t)(i * 384 + j) * 1024;
#pragma unroll
    for (int qq = 0; qq < 16; ++qq) {
        const int e = (t16 + qq * 16) * 4;
        const float* sp = Ds + (ii * 32 + (e >> 5)) * 132 + jj * 32 + (e & 31);
        float4 v = *(const float4*)sp;
        v.x = f2tf32(v.x); v.y = f2tf32(v.y); v.z = f2tf32(v.z); v.w = f2tf32(v.w);
        *(float4*)(dst + e) = v;
    }
}

// ============================================================================
// gemm2: z[p][n] = sum_e A[p][e]*Wo[e][n] + bias -> rmsnorm(g_out)
// 128x128x1024, 3-stage pipeline.
// ============================================================================
__global__ __launch_bounds__(256, 2)
void gemm2_kernel(const float* __restrict__ bo, const float* __restrict__ gout,
                  float* __restrict__ out) {
    extern __shared__ float sm[];
    const int tid = threadIdx.x, w = tid >> 5, l = tid & 31;
    const int mw = w >> 2, nw = w & 3, lg = l >> 2, lm4 = l & 3;
    const int p_base = blockIdx.x * 128;
    const uint32_t smb = smem_u32(sm);

    float acc[4][4][4] = {};

    int srow[4], sq[4];
    uint32_t sdst[4];
#pragma unroll
    for (int v = 0; v < 4; ++v) {
        const int fl = v * 256 + tid;
        srow[v] = fl >> 3;
        sq[v]   = fl & 7;
        sdst[v] = (uint32_t)((srow[v] * 8 + (sq[v] ^ (srow[v] & 7))) * 16);
    }

#define G2_STAGE(ks, buf) do {                                                  \
    const uint32_t bofs = smb + (uint32_t)(buf) * 32768u;                       \
    _Pragma("unroll")                                                           \
    for (int v = 0; v < 4; ++v) {                                               \
        const float* sA = g_a + (size_t)(p_base + srow[v]) * 1024 + (ks) * 32 + sq[v] * 4; \
        const int fl = v * 256 + tid;                                           \
        const float* sB = g_wo + (ks) * 4096 + fl * 4;                          \
        CP_ASYNC16(bofs + sdst[v], sA);                                         \
        CP_ASYNC16(bofs + 16384 + (uint32_t)(fl * 16), sB);                     \
    }                                                                           \
    CP_COMMIT();                                                                \
} while (0)

    G2_STAGE(0, 0);
    G2_STAGE(1, 1);
#pragma unroll 4
    for (int ks = 0; ks < 32; ++ks) {
        if (ks + 1 < 32) CP_WAIT1(); else CP_WAIT0();
        __syncthreads();
        if (ks + 2 < 32) G2_STAGE(ks + 2, (ks + 2) % 3);
        const float* As = sm + (ks % 3) * 8192;
        mma_chunk(As, As + 4096, acc, mw, nw, lg, lm4);
    }
    __syncthreads();

    float* Ds = sm;
#pragma unroll
    for (int mi = 0; mi < 4; ++mi) {
        const int r0 = mw * 64 + mi * 16 + lg;
#pragma unroll
        for (int ni = 0; ni < 4; ++ni) {
            const int c0 = nw * 32 + ni * 8 + lm4 * 2;
            *(float2*)(Ds + r0 * 132 + c0)       = make_float2(acc[mi][ni][0], acc[mi][ni][1]);
            *(float2*)(Ds + (r0 + 8) * 132 + c0) = make_float2(acc[mi][ni][2], acc[mi][ni][3]);
        }
    }
    __syncthreads();

    const int row = tid >> 1, h = tid & 1;
    const float* rp = Ds + row * 132 + h * 64;
    float fv[64];
    float ssq = 0.0f;
#pragma unroll
    for (int q = 0; q < 16; ++q) {
        float4 v = *(const float4*)(rp + q * 4);
        const float4 bb = __ldg((const float4*)(bo + h * 64 + q * 4));
        fv[q * 4 + 0] = v.x + bb.x;
        fv[q * 4 + 1] = v.y + bb.y;
        fv[q * 4 + 2] = v.z + bb.z;
        fv[q * 4 + 3] = v.w + bb.w;
        ssq = fmaf(fv[q*4+0], fv[q*4+0], ssq);
        ssq = fmaf(fv[q*4+1], fv[q*4+1], ssq);
        ssq = fmaf(fv[q*4+2], fv[q*4+2], ssq);
        ssq = fmaf(fv[q*4+3], fv[q*4+3], ssq);
    }
    ssq += __shfl_xor_sync(~0u, ssq, 1);
    const float sc = rsqrtf(ssq * (1.0f / 128.0f) + EPSV);
    float* op = out + (size_t)(p_base + row) * 128 + h * 64;
#pragma unroll
    for (int q = 0; q < 16; ++q) {
        const float4 gg = __ldg((const float4*)(gout + h * 64 + q * 4));
        float4 v;
        v.x = fv[q * 4 + 0] * sc * gg.x;
        v.y = fv[q * 4 + 1] * sc * gg.y;
        v.z = fv[q * 4 + 2] * sc * gg.z;
        v.w = fv[q * 4 + 3] * sc * gg.w;
        *(float4*)(op + q * 4) = v;
    }
}

// ============================================================================
extern "C" void kernel_launch(void* const* d_in, const int* in_sizes, int n_in,
                              void* d_out, int out_size) {
    const float* m    = (const float*)d_in[0];
    const float* g_in = (const float*)d_in[1];
    const float* Wq   = (const float*)d_in[2];
    const float* bq   = (const float*)d_in[3];
    const float* Wk   = (const float*)d_in[4];
    const float* bk   = (const float*)d_in[5];
    const float* Wo   = (const float*)d_in[6];
    const float* bo   = (const float*)d_in[7];
    const float* gout = (const float*)d_in[8];
    float* out = (float*)d_out;

    cudaFuncSetAttribute(proj_kernel,  cudaFuncAttributeMaxDynamicSharedMemorySize, 98304);
    cudaFuncSetAttribute(gemm1_kernel, cudaFuncAttributeMaxDynamicSharedMemorySize, 98304);
    cudaFuncSetAttribute(gemm2_kernel, cudaFuncAttributeMaxDynamicSharedMemorySize, 98304);

    proj_kernel<<<(256 * 384) / 32, 256, 98304>>>(m, g_in, Wq, bq, Wk, bk);
    wot_kernel<<<32, 128>>>(Wo);
    gemm1_kernel<<<dim3(96, 96), 256, 98304>>>();
    gemm2_kernel<<<1152, 256, 98304>>>(bo, gout, out);
}

// round 6
// speedup vs baseline: 6.8287x; 1.0338x over previous
#include <cuda_runtime.h>
#include <cstdint>
#include <cstddef>

#define EPSV 1e-5f

// g_q/g_k: [(s*32+c)*256 + b]  — GEMM1 operand rows (m=(s,c)), K(=b)-contiguous
__device__ float g_q[384 * 32 * 256];
__device__ float g_k[384 * 32 * 256];
// g_wo: 32 k-slices, each the ready smem image: [n=128][32 floats, XOR-swizzled]
__device__ float g_wo[32 * 4096];
// g_a: [p = i*384+j][e = c*32+d]  row-major — GEMM2 A operand
__device__ float g_a[150994944];  // 147456 * 1024 floats = 604 MB

// ---------------- helpers ----------------
__device__ __forceinline__ uint32_t smem_u32(const void* p) {
    uint32_t a;
    asm("{ .reg .u64 t; cvta.to.shared.u64 t, %1; cvt.u32.u64 %0, t; }" : "=r"(a) : "l"(p));
    return a;
}
__device__ __forceinline__ float f2tf32(float x) {
    uint32_t r;
    asm("cvt.rna.tf32.f32 %0, %1;" : "=r"(r) : "f"(x));
    return __uint_as_float(r);
}
#define CP_ASYNC16(dst, src) \
    asm volatile("cp.async.cg.shared.global [%0], [%1], 16;" :: "r"(dst), "l"(src))
#define CP_COMMIT() asm volatile("cp.async.commit_group;")
#define CP_WAIT1()  asm volatile("cp.async.wait_group 1;")
#define CP_WAIT0()  asm volatile("cp.async.wait_group 0;")

#define LDSM_X4(r0, r1, r2, r3, addr) \
    asm volatile("ldmatrix.sync.aligned.m8n8.x4.shared.b16 {%0,%1,%2,%3}, [%4];" \
                 : "=r"(r0), "=r"(r1), "=r"(r2), "=r"(r3) : "r"(addr))

__device__ __forceinline__ void mma_tf32(float* d, uint32_t a0, uint32_t a1,
                                         uint32_t a2, uint32_t a3,
                                         uint32_t b0, uint32_t b1) {
    asm volatile(
        "mma.sync.aligned.m16n8k8.row.col.f32.tf32.tf32.f32 "
        "{%0,%1,%2,%3}, {%4,%5,%6,%7}, {%8,%9}, {%0,%1,%2,%3};"
        : "+f"(d[0]), "+f"(d[1]), "+f"(d[2]), "+f"(d[3])
        : "r"(a0), "r"(a1), "r"(a2), "r"(a3), "r"(b0), "r"(b1));
}

// ============================================================================
// proj: rmsnorm(m)*g_in -> q/k projections -> tf32-rounded transposed store
// ============================================================================
__global__ __launch_bounds__(256, 2)
void proj_kernel(const float* __restrict__ m, const float* __restrict__ g_in,
                 const float* __restrict__ Wq, const float* __restrict__ bq,
                 const float* __restrict__ Wk, const float* __restrict__ bk)
{
    extern __shared__ float sm[];
    float* Wq_s = sm;
    float* Wk_s = sm + 8192;
    float* mn_s = sm + 16384;
    const int tid = threadIdx.x, warp = tid >> 5, lane = tid & 31;
    const float4* Wq4 = (const float4*)Wq;
    const float4* Wk4 = (const float4*)Wk;
#pragma unroll
    for (int v = 0; v < 8; ++v) {
        ((float4*)Wq_s)[v * 256 + tid] = Wq4[v * 256 + tid];
        ((float4*)Wk_s)[v * 256 + tid] = Wk4[v * 256 + tid];
    }
    const int rb = (blockIdx.x * 8 + warp) * 4;
    float* mw = mn_s + warp * 1024;
    const float4 gi0 = ((const float4*)g_in)[lane * 2];
    const float4 gi1 = ((const float4*)g_in)[lane * 2 + 1];
    float vals[4][8], ssum[4];
#pragma unroll
    for (int r = 0; r < 4; ++r) {
        const float4* mp = (const float4*)(m + (size_t)(rb + r) * 256);
        float4 a = mp[lane * 2], b = mp[lane * 2 + 1];
        vals[r][0] = a.x; vals[r][1] = a.y; vals[r][2] = a.z; vals[r][3] = a.w;
        vals[r][4] = b.x; vals[r][5] = b.y; vals[r][6] = b.z; vals[r][7] = b.w;
        ssum[r] = a.x*a.x + a.y*a.y + a.z*a.z + a.w*a.w
                + b.x*b.x + b.y*b.y + b.z*b.z + b.w*b.w;
    }
#pragma unroll
    for (int r = 0; r < 4; ++r) {
        float s = ssum[r];
#pragma unroll
        for (int o = 16; o >= 1; o >>= 1) s += __shfl_xor_sync(~0u, s, o);
        const float sc = rsqrtf(s * (1.0f / 256.0f) + EPSV);
        float4 o0, o1;
        o0.x = vals[r][0]*sc*gi0.x; o0.y = vals[r][1]*sc*gi0.y;
        o0.z = vals[r][2]*sc*gi0.z; o0.w = vals[r][3]*sc*gi0.w;
        o1.x = vals[r][4]*sc*gi1.x; o1.y = vals[r][5]*sc*gi1.y;
        o1.z = vals[r][6]*sc*gi1.z; o1.w = vals[r][7]*sc*gi1.w;
        ((float4*)(mw + r * 256))[lane * 2]     = o0;
        ((float4*)(mw + r * 256))[lane * 2 + 1] = o1;
    }
    __syncthreads();
    float aq[4], ak[4];
    const float bqv = __ldg(bq + lane), bkv = __ldg(bk + lane);
#pragma unroll
    for (int r = 0; r < 4; ++r) { aq[r] = bqv; ak[r] = bkv; }
#pragma unroll 4
    for (int mm = 0; mm < 256; ++mm) {
        const float wq = Wq_s[mm * 32 + lane], wk = Wk_s[mm * 32 + lane];
#pragma unroll
        for (int r = 0; r < 4; ++r) {
            const float x = mw[r * 256 + mm];
            aq[r] = fmaf(x, wq, aq[r]);
            ak[r] = fmaf(x, wk, ak[r]);
        }
    }
#pragma unroll
    for (int r = 0; r < 4; ++r) {
        const int row = rb + r, b = row / 384, s = row - b * 384;
        g_q[(size_t)(s * 32 + lane) * 256 + b] = f2tf32(aq[r]);
        g_k[(size_t)(s * 32 + lane) * 256 + b] = f2tf32(ak[r]);
    }
}

// ============================================================================
// wot: Wo[e=ks*32+kk][z=n] -> g_wo[ks][n*32 + swiz(kk,n)] (tf32-rounded)
// ============================================================================
__global__ void wot_kernel(const float* __restrict__ Wo) {
    const int ks = blockIdx.x, n = threadIdx.x;
    float* dst = g_wo + ks * 4096 + n * 32;
    const int n7 = n & 7;
#pragma unroll
    for (int kk = 0; kk < 32; ++kk) {
        const float v = f2tf32(__ldg(Wo + (size_t)(ks * 32 + kk) * 128 + n));
        dst[(((kk >> 2) ^ n7) << 2) | (kk & 3)] = v;
    }
}

// ============================================================================
// ldmatrix address precompute + one 32-k chunk of 128x128 MMA.
// A tile: rows (m) 0..127 x 32 k-floats, swizzled group = (k>>2)^(row&7).
// aOff[mi]: lane-specific byte offset (within stage) for ldmatrix.x4 covering
//   the 16x8 tf32 A fragment; bOff[nip]: covers two n8 B fragments.
// Per s-step: addr = stage_base + (off ^ (s<<5)).
// ============================================================================
struct LdsmAddrs { uint32_t a[4]; uint32_t b[2]; };

__device__ __forceinline__ LdsmAddrs ldsm_prep(int w, int l) {
    const int mw = w >> 2, nw = w & 3;
    const int r7 = l & 7;
    LdsmAddrs o;
    const int kbitA = (l >> 4) & 1;     // A tiles 2,3 -> k-group+1
    const int rhiA  = (l >> 3) & 1;     // A tiles 1,3 -> rows+8
#pragma unroll
    for (int mi = 0; mi < 4; ++mi) {
        const int row = mw * 64 + mi * 16 + rhiA * 8 + r7;
        o.a[mi] = (uint32_t)(row * 128 + ((r7 ^ kbitA) << 4));
    }
    const int kbitB = (l >> 3) & 1;     // B tiles 1,3 -> k-group+1
    const int rhiB  = (l >> 4) & 1;     // B tiles 2,3 -> n-rows+8
#pragma unroll
    for (int nip = 0; nip < 2; ++nip) {
        const int row = nw * 32 + nip * 16 + rhiB * 8 + r7;
        o.b[nip] = (uint32_t)(16384 + row * 128 + ((r7 ^ kbitB) << 4));
    }
    return o;
}

__device__ __forceinline__ void mma_chunk(uint32_t stage, const LdsmAddrs& ad,
                                          float acc[4][4][4]) {
#pragma unroll
    for (int s = 0; s < 4; ++s) {
        const uint32_t sx = (uint32_t)(s << 5);
        uint32_t b0[4], b1[4];
        LDSM_X4(b0[0], b1[0], b0[1], b1[1], stage + (ad.b[0] ^ sx));
        LDSM_X4(b0[2], b1[2], b0[3], b1[3], stage + (ad.b[1] ^ sx));
#pragma unroll
        for (int mi = 0; mi < 4; ++mi) {
            uint32_t A0, A1, A2, A3;
            LDSM_X4(A0, A1, A2, A3, stage + (ad.a[mi] ^ sx));
#pragma unroll
            for (int ni = 0; ni < 4; ++ni)
                mma_tf32(acc[mi][ni], A0, A1, A2, A3, b0[ni], b1[ni]);
        }
    }
}

// ============================================================================
// gemm1: D[(i,c)][(j,d)] = sum_b q*k  — 128x128x256, 3-stage pipeline.
// ============================================================================
__global__ __launch_bounds__(256, 2)
void gemm1_kernel() {
    extern __shared__ float sm[];
    const int tid = threadIdx.x, w = tid >> 5, l = tid & 31;
    const int mw = w >> 2, nw = w & 3, lg = l >> 2, lm4 = l & 3;
    const int irow = blockIdx.y * 128, jrow = blockIdx.x * 128;
    const uint32_t smb = smem_u32(sm);
    const LdsmAddrs ad = ldsm_prep(w, l);

    float acc[4][4][4] = {};

    int srow[4], sq[4];
    uint32_t sdst[4];
#pragma unroll
    for (int v = 0; v < 4; ++v) {
        const int fl = v * 256 + tid;
        srow[v] = fl >> 3;
        sq[v]   = fl & 7;
        sdst[v] = (uint32_t)((srow[v] * 8 + (sq[v] ^ (srow[v] & 7))) * 16);
    }

#define G1_STAGE(ks, buf) do {                                                  \
    const uint32_t bofs = smb + (uint32_t)(buf) * 32768u;                       \
    _Pragma("unroll")                                                           \
    for (int v = 0; v < 4; ++v) {                                               \
        const float* sA = g_q + (size_t)(irow + srow[v]) * 256 + (ks) * 32 + sq[v] * 4; \
        const float* sB = g_k + (size_t)(jrow + srow[v]) * 256 + (ks) * 32 + sq[v] * 4; \
        CP_ASYNC16(bofs + sdst[v], sA);                                         \
        CP_ASYNC16(bofs + 16384 + sdst[v], sB);                                 \
    }                                                                           \
    CP_COMMIT();                                                                \
} while (0)

    G1_STAGE(0, 0);
    G1_STAGE(1, 1);
#pragma unroll
    for (int ks = 0; ks < 8; ++ks) {
        if (ks + 1 < 8) CP_WAIT1(); else CP_WAIT0();
        __syncthreads();
        if (ks + 2 < 8) G1_STAGE(ks + 2, (ks + 2) % 3);
        mma_chunk(smb + (uint32_t)(ks % 3) * 32768u, ad, acc);
    }
    __syncthreads();

    float* Ds = sm;
#pragma unroll
    for (int mi = 0; mi < 4; ++mi) {
        const int r0 = mw * 64 + mi * 16 + lg;
#pragma unroll
        for (int ni = 0; ni < 4; ++ni) {
            const int c0 = nw * 32 + ni * 8 + lm4 * 2;
            *(float2*)(Ds + r0 * 132 + c0)       = make_float2(acc[mi][ni][0], acc[mi][ni][1]);
            *(float2*)(Ds + (r0 + 8) * 132 + c0) = make_float2(acc[mi][ni][2], acc[mi][ni][3]);
        }
    }
    __syncthreads();

    const int pp = tid >> 4, t16 = tid & 15;
    const int ii = pp >> 2, jj = pp & 3;
    const int i = blockIdx.y * 4 + ii, j = blockIdx.x * 4 + jj;
    float* dst = g_a + (size_t)(i * 384 + j) * 1024;
#pragma unroll
    for (int qq = 0; qq < 16; ++qq) {
        const int e = (t16 + qq * 16) * 4;
        const float* sp = Ds + (ii * 32 + (e >> 5)) * 132 + jj * 32 + (e & 31);
        float4 v = *(const float4*)sp;
        v.x = f2tf32(v.x); v.y = f2tf32(v.y); v.z = f2tf32(v.z); v.w = f2tf32(v.w);
        *(float4*)(dst + e) = v;
    }
}

// ============================================================================
// gemm2: z[p][n] = sum_e A[p][e]*Wo[e][n] + bias -> rmsnorm(g_out)
// 128x128x1024, 3-stage pipeline.
// ============================================================================
__global__ __launch_bounds__(256, 2)
void gemm2_kernel(const float* __restrict__ bo, const float* __restrict__ gout,
                  float* __restrict__ out) {
    extern __shared__ float sm[];
    const int tid = threadIdx.x, w = tid >> 5, l = tid & 31;
    const int mw = w >> 2, nw = w & 3, lg = l >> 2, lm4 = l & 3;
    const int p_base = blockIdx.x * 128;
    const uint32_t smb = smem_u32(sm);
    const LdsmAddrs ad = ldsm_prep(w, l);

    float acc[4][4][4] = {};

    int srow[4], sq[4];
    uint32_t sdst[4];
#pragma unroll
    for (int v = 0; v < 4; ++v) {
        const int fl = v * 256 + tid;
        srow[v] = fl >> 3;
        sq[v]   = fl & 7;
        sdst[v] = (uint32_t)((srow[v] * 8 + (sq[v] ^ (srow[v] & 7))) * 16);
    }

#define G2_STAGE(ks, buf) do {                                                  \
    const uint32_t bofs = smb + (uint32_t)(buf) * 32768u;                       \
    _Pragma("unroll")                                                           \
    for (int v = 0; v < 4; ++v) {                                               \
        const float* sA = g_a + (size_t)(p_base + srow[v]) * 1024 + (ks) * 32 + sq[v] * 4; \
        const int fl = v * 256 + tid;                                           \
        const float* sB = g_wo + (ks) * 4096 + fl * 4;                          \
        CP_ASYNC16(bofs + sdst[v], sA);                                         \
        CP_ASYNC16(bofs + 16384 + (uint32_t)(fl * 16), sB);                     \
    }                                                                           \
    CP_COMMIT();                                                                \
} while (0)

    G2_STAGE(0, 0);
    G2_STAGE(1, 1);
#pragma unroll 4
    for (int ks = 0; ks < 32; ++ks) {
        if (ks + 1 < 32) CP_WAIT1(); else CP_WAIT0();
        __syncthreads();
        if (ks + 2 < 32) G2_STAGE(ks + 2, (ks + 2) % 3);
        mma_chunk(smb + (uint32_t)(ks % 3) * 32768u, ad, acc);
    }
    __syncthreads();

    float* Ds = sm;
#pragma unroll
    for (int mi = 0; mi < 4; ++mi) {
        const int r0 = mw * 64 + mi * 16 + lg;
#pragma unroll
        for (int ni = 0; ni < 4; ++ni) {
            const int c0 = nw * 32 + ni * 8 + lm4 * 2;
            *(float2*)(Ds + r0 * 132 + c0)       = make_float2(acc[mi][ni][0], acc[mi][ni][1]);
            *(float2*)(Ds + (r0 + 8) * 132 + c0) = make_float2(acc[mi][ni][2], acc[mi][ni][3]);
        }
    }
    __syncthreads();

    const int row = tid >> 1, h = tid & 1;
    const float* rp = Ds + row * 132 + h * 64;
    float fv[64];
    float ssq = 0.0f;
#pragma unroll
    for (int q = 0; q < 16; ++q) {
        float4 v = *(const float4*)(rp + q * 4);
        const float4 bb = __ldg((const float4*)(bo + h * 64 + q * 4));
        fv[q * 4 + 0] = v.x + bb.x;
        fv[q * 4 + 1] = v.y + bb.y;
        fv[q * 4 + 2] = v.z + bb.z;
        fv[q * 4 + 3] = v.w + bb.w;
        ssq = fmaf(fv[q*4+0], fv[q*4+0], ssq);
        ssq = fmaf(fv[q*4+1], fv[q*4+1], ssq);
        ssq = fmaf(fv[q*4+2], fv[q*4+2], ssq);
        ssq = fmaf(fv[q*4+3], fv[q*4+3], ssq);
    }
    ssq += __shfl_xor_sync(~0u, ssq, 1);
    const float sc = rsqrtf(ssq * (1.0f / 128.0f) + EPSV);
    float* op = out + (size_t)(p_base + row) * 128 + h * 64;
#pragma unroll
    for (int q = 0; q < 16; ++q) {
        const float4 gg = __ldg((const float4*)(gout + h * 64 + q * 4));
        float4 v;
        v.x = fv[q * 4 + 0] * sc * gg.x;
        v.y = fv[q * 4 + 1] * sc * gg.y;
        v.z = fv[q * 4 + 2] * sc * gg.z;
        v.w = fv[q * 4 + 3] * sc * gg.w;
        *(float4*)(op + q * 4) = v;
    }
}

// ============================================================================
extern "C" void kernel_launch(void* const* d_in, const int* in_sizes, int n_in,
                              void* d_out, int out_size) {
    const float* m    = (const float*)d_in[0];
    const float* g_in = (const float*)d_in[1];
    const float* Wq   = (const float*)d_in[2];
    const float* bq   = (const float*)d_in[3];
    const float* Wk   = (const float*)d_in[4];
    const float* bk   = (const float*)d_in[5];
    const float* Wo   = (const float*)d_in[6];
    const float* bo   = (const float*)d_in[7];
    const float* gout = (const float*)d_in[8];
    float* out = (float*)d_out;

    cudaFuncSetAttribute(proj_kernel,  cudaFuncAttributeMaxDynamicSharedMemorySize, 98304);
    cudaFuncSetAttribute(gemm1_kernel, cudaFuncAttributeMaxDynamicSharedMemorySize, 98304);
    cudaFuncSetAttribute(gemm2_kernel, cudaFuncAttributeMaxDynamicSharedMemorySize, 98304);

    proj_kernel<<<(256 * 384) / 32, 256, 98304>>>(m, g_in, Wq, bq, Wk, bk);
    wot_kernel<<<32, 128>>>(Wo);
    gemm1_kernel<<<dim3(96, 96), 256, 98304>>>();
    gemm2_kernel<<<1152, 256, 98304>>>(bo, gout, out);
}

// round 7
// speedup vs baseline: 7.1296x; 1.0441x over previous
#include <cuda_runtime.h>
#include <cstdint>
#include <cstddef>

#define EPSV 1e-5f

// g_q/g_k: [(s*32+c)*256 + b]  — GEMM1 operand rows (m=(s,c)), K(=b)-contiguous
__device__ float g_q[384 * 32 * 256];
__device__ float g_k[384 * 32 * 256];
// g_wo: 32 k-slices, each the ready smem image: [n=128][32 floats, XOR-swizzled]
__device__ float g_wo[32 * 4096];
// g_a: [p = i*384+j][e = c*32+d]  row-major — GEMM2 A operand
__device__ float g_a[150994944];  // 147456 * 1024 floats = 604 MB

// ---------------- helpers ----------------
__device__ __forceinline__ uint32_t smem_u32(const void* p) {
    uint32_t a;
    asm("{ .reg .u64 t; cvta.to.shared.u64 t, %1; cvt.u32.u64 %0, t; }" : "=r"(a) : "l"(p));
    return a;
}
__device__ __forceinline__ float f2tf32(float x) {
    uint32_t r;
    asm("cvt.rna.tf32.f32 %0, %1;" : "=r"(r) : "f"(x));
    return __uint_as_float(r);
}
#define CP_ASYNC16(dst, src) \
    asm volatile("cp.async.cg.shared.global [%0], [%1], 16;" :: "r"(dst), "l"(src))
#define CP_COMMIT() asm volatile("cp.async.commit_group;")
#define CP_WAIT1()  asm volatile("cp.async.wait_group 1;")
#define CP_WAIT0()  asm volatile("cp.async.wait_group 0;")

#define LDSM_X4(r0, r1, r2, r3, addr) \
    asm volatile("ldmatrix.sync.aligned.m8n8.x4.shared.b16 {%0,%1,%2,%3}, [%4];" \
                 : "=r"(r0), "=r"(r1), "=r"(r2), "=r"(r3) : "r"(addr))

__device__ __forceinline__ void mma_tf32(float* d, uint32_t a0, uint32_t a1,
                                         uint32_t a2, uint32_t a3,
                                         uint32_t b0, uint32_t b1) {
    asm volatile(
        "mma.sync.aligned.m16n8k8.row.col.f32.tf32.tf32.f32 "
        "{%0,%1,%2,%3}, {%4,%5,%6,%7}, {%8,%9}, {%0,%1,%2,%3};"
        : "+f"(d[0]), "+f"(d[1]), "+f"(d[2]), "+f"(d[3])
        : "r"(a0), "r"(a1), "r"(a2), "r"(a3), "r"(b0), "r"(b1));
}

// ============================================================================
// proj: rmsnorm(m)*g_in -> q/k projections -> tf32-rounded transposed store
// ============================================================================
__global__ __launch_bounds__(256, 2)
void proj_kernel(const float* __restrict__ m, const float* __restrict__ g_in,
                 const float* __restrict__ Wq, const float* __restrict__ bq,
                 const float* __restrict__ Wk, const float* __restrict__ bk)
{
    extern __shared__ float sm[];
    float* Wq_s = sm;
    float* Wk_s = sm + 8192;
    float* mn_s = sm + 16384;
    const int tid = threadIdx.x, warp = tid >> 5, lane = tid & 31;
    const float4* Wq4 = (const float4*)Wq;
    const float4* Wk4 = (const float4*)Wk;
#pragma unroll
    for (int v = 0; v < 8; ++v) {
        ((float4*)Wq_s)[v * 256 + tid] = Wq4[v * 256 + tid];
        ((float4*)Wk_s)[v * 256 + tid] = Wk4[v * 256 + tid];
    }
    const int rb = (blockIdx.x * 8 + warp) * 4;
    float* mw = mn_s + warp * 1024;
    const float4 gi0 = ((const float4*)g_in)[lane * 2];
    const float4 gi1 = ((const float4*)g_in)[lane * 2 + 1];
    float vals[4][8], ssum[4];
#pragma unroll
    for (int r = 0; r < 4; ++r) {
        const float4* mp = (const float4*)(m + (size_t)(rb + r) * 256);
        float4 a = mp[lane * 2], b = mp[lane * 2 + 1];
        vals[r][0] = a.x; vals[r][1] = a.y; vals[r][2] = a.z; vals[r][3] = a.w;
        vals[r][4] = b.x; vals[r][5] = b.y; vals[r][6] = b.z; vals[r][7] = b.w;
        ssum[r] = a.x*a.x + a.y*a.y + a.z*a.z + a.w*a.w
                + b.x*b.x + b.y*b.y + b.z*b.z + b.w*b.w;
    }
#pragma unroll
    for (int r = 0; r < 4; ++r) {
        float s = ssum[r];
#pragma unroll
        for (int o = 16; o >= 1; o >>= 1) s += __shfl_xor_sync(~0u, s, o);
        const float sc = rsqrtf(s * (1.0f / 256.0f) + EPSV);
        float4 o0, o1;
        o0.x = vals[r][0]*sc*gi0.x; o0.y = vals[r][1]*sc*gi0.y;
        o0.z = vals[r][2]*sc*gi0.z; o0.w = vals[r][3]*sc*gi0.w;
        o1.x = vals[r][4]*sc*gi1.x; o1.y = vals[r][5]*sc*gi1.y;
        o1.z = vals[r][6]*sc*gi1.z; o1.w = vals[r][7]*sc*gi1.w;
        ((float4*)(mw + r * 256))[lane * 2]     = o0;
        ((float4*)(mw + r * 256))[lane * 2 + 1] = o1;
    }
    __syncthreads();
    float aq[4], ak[4];
    const float bqv = __ldg(bq + lane), bkv = __ldg(bk + lane);
#pragma unroll
    for (int r = 0; r < 4; ++r) { aq[r] = bqv; ak[r] = bkv; }
#pragma unroll 4
    for (int mm = 0; mm < 256; ++mm) {
        const float wq = Wq_s[mm * 32 + lane], wk = Wk_s[mm * 32 + lane];
#pragma unroll
        for (int r = 0; r < 4; ++r) {
            const float x = mw[r * 256 + mm];
            aq[r] = fmaf(x, wq, aq[r]);
            ak[r] = fmaf(x, wk, ak[r]);
        }
    }
#pragma unroll
    for (int r = 0; r < 4; ++r) {
        const int row = rb + r, b = row / 384, s = row - b * 384;
        g_q[(size_t)(s * 32 + lane) * 256 + b] = f2tf32(aq[r]);
        g_k[(size_t)(s * 32 + lane) * 256 + b] = f2tf32(ak[r]);
    }
}

// ============================================================================
// wot: Wo[e=ks*32+kk][z=n] -> g_wo[ks][n*32 + swiz(kk,n)] (tf32-rounded)
// ============================================================================
__global__ void wot_kernel(const float* __restrict__ Wo) {
    const int ks = blockIdx.x, n = threadIdx.x;
    float* dst = g_wo + ks * 4096 + n * 32;
    const int n7 = n & 7;
#pragma unroll
    for (int kk = 0; kk < 32; ++kk) {
        const float v = f2tf32(__ldg(Wo + (size_t)(ks * 32 + kk) * 128 + n));
        dst[(((kk >> 2) ^ n7) << 2) | (kk & 3)] = v;
    }
}

// ============================================================================
// ldmatrix address precompute + one 32-k chunk of 128x128 MMA.
// ============================================================================
struct LdsmAddrs { uint32_t a[4]; uint32_t b[2]; };

__device__ __forceinline__ LdsmAddrs ldsm_prep(int w, int l) {
    const int mw = w >> 2, nw = w & 3;
    const int r7 = l & 7;
    LdsmAddrs o;
    const int kbitA = (l >> 4) & 1;
    const int rhiA  = (l >> 3) & 1;
#pragma unroll
    for (int mi = 0; mi < 4; ++mi) {
        const int row = mw * 64 + mi * 16 + rhiA * 8 + r7;
        o.a[mi] = (uint32_t)(row * 128 + ((r7 ^ kbitA) << 4));
    }
    const int kbitB = (l >> 3) & 1;
    const int rhiB  = (l >> 4) & 1;
#pragma unroll
    for (int nip = 0; nip < 2; ++nip) {
        const int row = nw * 32 + nip * 16 + rhiB * 8 + r7;
        o.b[nip] = (uint32_t)(16384 + row * 128 + ((r7 ^ kbitB) << 4));
    }
    return o;
}

__device__ __forceinline__ void mma_chunk(uint32_t stage, const LdsmAddrs& ad,
                                          float acc[4][4][4]) {
#pragma unroll
    for (int s = 0; s < 4; ++s) {
        const uint32_t sx = (uint32_t)(s << 5);
        uint32_t b0[4], b1[4];
        LDSM_X4(b0[0], b1[0], b0[1], b1[1], stage + (ad.b[0] ^ sx));
        LDSM_X4(b0[2], b1[2], b0[3], b1[3], stage + (ad.b[1] ^ sx));
#pragma unroll
        for (int mi = 0; mi < 4; ++mi) {
            uint32_t A0, A1, A2, A3;
            LDSM_X4(A0, A1, A2, A3, stage + (ad.a[mi] ^ sx));
#pragma unroll
            for (int ni = 0; ni < 4; ++ni)
                mma_tf32(acc[mi][ni], A0, A1, A2, A3, b0[ni], b1[ni]);
        }
    }
}

// ============================================================================
// gemm1: D[(i,c)][(j,d)] = sum_b q*k  — 128x128x256, 3-stage pipeline.
// Epilogue: DIRECT register->global scatter (32B-sector aligned quads),
// streaming stores, no smem staging, no extra barriers.
// ============================================================================
__global__ __launch_bounds__(256, 2)
void gemm1_kernel() {
    extern __shared__ float sm[];
    const int tid = threadIdx.x, w = tid >> 5, l = tid & 31;
    const int mw = w >> 2, nw = w & 3, lg = l >> 2, lm4 = l & 3;
    const int irow = blockIdx.y * 128, jrow = blockIdx.x * 128;
    const uint32_t smb = smem_u32(sm);
    const LdsmAddrs ad = ldsm_prep(w, l);

    float acc[4][4][4] = {};

    int srow[4], sq[4];
    uint32_t sdst[4];
#pragma unroll
    for (int v = 0; v < 4; ++v) {
        const int fl = v * 256 + tid;
        srow[v] = fl >> 3;
        sq[v]   = fl & 7;
        sdst[v] = (uint32_t)((srow[v] * 8 + (sq[v] ^ (srow[v] & 7))) * 16);
    }

#define G1_STAGE(ks, buf) do {                                                  \
    const uint32_t bofs = smb + (uint32_t)(buf) * 32768u;                       \
    _Pragma("unroll")                                                           \
    for (int v = 0; v < 4; ++v) {                                               \
        const float* sA = g_q + (size_t)(irow + srow[v]) * 256 + (ks) * 32 + sq[v] * 4; \
        const float* sB = g_k + (size_t)(jrow + srow[v]) * 256 + (ks) * 32 + sq[v] * 4; \
        CP_ASYNC16(bofs + sdst[v], sA);                                         \
        CP_ASYNC16(bofs + 16384 + sdst[v], sB);                                 \
    }                                                                           \
    CP_COMMIT();                                                                \
} while (0)

    G1_STAGE(0, 0);
    G1_STAGE(1, 1);
#pragma unroll
    for (int ks = 0; ks < 8; ++ks) {
        if (ks + 1 < 8) CP_WAIT1(); else CP_WAIT0();
        __syncthreads();
        if (ks + 2 < 8) G1_STAGE(ks + 2, (ks + 2) % 3);
        mma_chunk(smb + (uint32_t)(ks % 3) * 32768u, ad, acc);
    }

    // Direct epilogue: lane owns rows r=mw*64+mi*16+lg (+8), cols
    // c0=nw*32+ni*8+lm4*2 (+1). Map to g_a[p*1024 + c*32 + d]:
    //   p = (by*4 + r>>5)*384 + bx*4 + nw,  c = r&31,  d = ni*8 + lm4*2.
    const int j = blockIdx.x * 4 + nw;
#pragma unroll
    for (int mi = 0; mi < 4; ++mi) {
        const int r_lo = mw * 64 + mi * 16 + lg;
#pragma unroll
        for (int half = 0; half < 2; ++half) {
            const int r = r_lo + half * 8;
            const int i = blockIdx.y * 4 + (r >> 5);
            const int c = r & 31;
            float* base = g_a + (size_t)(i * 384 + j) * 1024 + c * 32 + lm4 * 2;
#pragma unroll
            for (int ni = 0; ni < 4; ++ni) {
                float2 v;
                v.x = f2tf32(acc[mi][ni][half * 2 + 0]);
                v.y = f2tf32(acc[mi][ni][half * 2 + 1]);
                __stcs((float2*)(base + ni * 8), v);
            }
        }
    }
}

// ============================================================================
// gemm2: z[p][n] = sum_e A[p][e]*Wo[e][n] + bias -> rmsnorm(g_out)
// 128x128x1024, 3-stage pipeline.
// ============================================================================
__global__ __launch_bounds__(256, 2)
void gemm2_kernel(const float* __restrict__ bo, const float* __restrict__ gout,
                  float* __restrict__ out) {
    extern __shared__ float sm[];
    const int tid = threadIdx.x, w = tid >> 5, l = tid & 31;
    const int mw = w >> 2, nw = w & 3, lg = l >> 2, lm4 = l & 3;
    const int p_base = blockIdx.x * 128;
    const uint32_t smb = smem_u32(sm);
    const LdsmAddrs ad = ldsm_prep(w, l);

    float acc[4][4][4] = {};

    int srow[4], sq[4];
    uint32_t sdst[4];
#pragma unroll
    for (int v = 0; v < 4; ++v) {
        const int fl = v * 256 + tid;
        srow[v] = fl >> 3;
        sq[v]   = fl & 7;
        sdst[v] = (uint32_t)((srow[v] * 8 + (sq[v] ^ (srow[v] & 7))) * 16);
    }

#define G2_STAGE(ks, buf) do {                                                  \
    const uint32_t bofs = smb + (uint32_t)(buf) * 32768u;                       \
    _Pragma("unroll")                                                           \
    for (int v = 0; v < 4; ++v) {                                               \
        const float* sA = g_a + (size_t)(p_base + srow[v]) * 1024 + (ks) * 32 + sq[v] * 4; \
        const int fl = v * 256 + tid;                                           \
        const float* sB = g_wo + (ks) * 4096 + fl * 4;                          \
        CP_ASYNC16(bofs + sdst[v], sA);                                         \
        CP_ASYNC16(bofs + 16384 + (uint32_t)(fl * 16), sB);                     \
    }                                                                           \
    CP_COMMIT();                                                                \
} while (0)

    G2_STAGE(0, 0);
    G2_STAGE(1, 1);
#pragma unroll 4
    for (int ks = 0; ks < 32; ++ks) {
        if (ks + 1 < 32) CP_WAIT1(); else CP_WAIT0();
        __syncthreads();
        if (ks + 2 < 32) G2_STAGE(ks + 2, (ks + 2) % 3);
        mma_chunk(smb + (uint32_t)(ks % 3) * 32768u, ad, acc);
    }
    __syncthreads();

    float* Ds = sm;
#pragma unroll
    for (int mi = 0; mi < 4; ++mi) {
        const int r0 = mw * 64 + mi * 16 + lg;
#pragma unroll
        for (int ni = 0; ni < 4; ++ni) {
            const int c0 = nw * 32 + ni * 8 + lm4 * 2;
            *(float2*)(Ds + r0 * 132 + c0)       = make_float2(acc[mi][ni][0], acc[mi][ni][1]);
            *(float2*)(Ds + (r0 + 8) * 132 + c0) = make_float2(acc[mi][ni][2], acc[mi][ni][3]);
        }
    }
    __syncthreads();

    const int row = tid >> 1, h = tid & 1;
    const float* rp = Ds + row * 132 + h * 64;
    float fv[64];
    float ssq = 0.0f;
#pragma unroll
    for (int q = 0; q < 16; ++q) {
        float4 v = *(const float4*)(rp + q * 4);
        const float4 bb = __ldg((const float4*)(bo + h * 64 + q * 4));
        fv[q * 4 + 0] = v.x + bb.x;
        fv[q * 4 + 1] = v.y + bb.y;
        fv[q * 4 + 2] = v.z + bb.z;
        fv[q * 4 + 3] = v.w + bb.w;
        ssq = fmaf(fv[q*4+0], fv[q*4+0], ssq);
        ssq = fmaf(fv[q*4+1], fv[q*4+1], ssq);
        ssq = fmaf(fv[q*4+2], fv[q*4+2], ssq);
        ssq = fmaf(fv[q*4+3], fv[q*4+3], ssq);
    }
    ssq += __shfl_xor_sync(~0u, ssq, 1);
    const float sc = rsqrtf(ssq * (1.0f / 128.0f) + EPSV);
    float* op = out + (size_t)(p_base + row) * 128 + h * 64;
#pragma unroll
    for (int q = 0; q < 16; ++q) {
        const float4 gg = __ldg((const float4*)(gout + h * 64 + q * 4));
        float4 v;
        v.x = fv[q * 4 + 0] * sc * gg.x;
        v.y = fv[q * 4 + 1] * sc * gg.y;
        v.z = fv[q * 4 + 2] * sc * gg.z;
        v.w = fv[q * 4 + 3] * sc * gg.w;
        *(float4*)(op + q * 4) = v;
    }
}

// ============================================================================
extern "C" void kernel_launch(void* const* d_in, const int* in_sizes, int n_in,
                              void* d_out, int out_size) {
    const float* m    = (const float*)d_in[0];
    const float* g_in = (const float*)d_in[1];
    const float* Wq   = (const float*)d_in[2];
    const float* bq   = (const float*)d_in[3];
    const float* Wk   = (const float*)d_in[4];
    const float* bk   = (const float*)d_in[5];
    const float* Wo   = (const float*)d_in[6];
    const float* bo   = (const float*)d_in[7];
    const float* gout = (const float*)d_in[8];
    float* out = (float*)d_out;

    cudaFuncSetAttribute(proj_kernel,  cudaFuncAttributeMaxDynamicSharedMemorySize, 98304);
    cudaFuncSetAttribute(gemm1_kernel, cudaFuncAttributeMaxDynamicSharedMemorySize, 98304);
    cudaFuncSetAttribute(gemm2_kernel, cudaFuncAttributeMaxDynamicSharedMemorySize, 98304);

    proj_kernel<<<(256 * 384) / 32, 256, 98304>>>(m, g_in, Wq, bq, Wk, bk);
    wot_kernel<<<32, 128>>>(Wo);
    gemm1_kernel<<<dim3(96, 96), 256, 98304>>>();
    gemm2_kernel<<<1152, 256, 98304>>>(bo, gout, out);
}